// round 2
// baseline (speedup 1.0000x reference)
#include <cuda_runtime.h>
#include <math.h>

#define NNODES 40962
#define NEDGES 327680
#define D 512
#define K1 1024
#define MPAD 41088  // 321 * 128

// Scratch (device globals: no allocations allowed)
__device__ float g_edge_sum[(size_t)NNODES * D];   // ~84 MB
__device__ float g_h[(size_t)MPAD * D];            // ~84 MB

__device__ __forceinline__ unsigned tf32_of(float f) {
    unsigned r;
    asm("cvt.rna.tf32.f32 %0, %1;" : "=r"(r) : "f"(f));
    return r;
}

__device__ __forceinline__ void mma_tf32(float c[4], const uint4& a, const uint2& b) {
    asm volatile(
        "mma.sync.aligned.m16n8k8.row.col.f32.tf32.tf32.f32 "
        "{%0,%1,%2,%3}, {%4,%5,%6,%7}, {%8,%9}, {%0,%1,%2,%3};\n"
        : "+f"(c[0]), "+f"(c[1]), "+f"(c[2]), "+f"(c[3])
        : "r"(a.x), "r"(a.y), "r"(a.z), "r"(a.w), "r"(b.x), "r"(b.y));
}

// ---------------------------------------------------------------------------
// K0: zero scatter target
// ---------------------------------------------------------------------------
__global__ void zero_kernel() {
    size_t i = (size_t)blockIdx.x * blockDim.x + threadIdx.x;
    size_t n4 = (size_t)NNODES * D / 4;
    if (i < n4) reinterpret_cast<float4*>(g_edge_sum)[i] = make_float4(0.f, 0.f, 0.f, 0.f);
}

// ---------------------------------------------------------------------------
// K1: scatter-add edge rows (atomics land in L2; target fits in 126MB L2)
// ---------------------------------------------------------------------------
__global__ void scatter_kernel(const float* __restrict__ edge_attr,
                               const int* __restrict__ edge_index) {
    int e = blockIdx.x;
    int t = threadIdx.x;
    int r = __ldg(&edge_index[NEDGES + e]);
    float4 v = *reinterpret_cast<const float4*>(edge_attr + (size_t)e * D + t * 4);
    float* dst = g_edge_sum + (size_t)r * D + t * 4;
    atomicAdd(dst + 0, v.x);
    atomicAdd(dst + 1, v.y);
    atomicAdd(dst + 2, v.z);
    atomicAdd(dst + 3, v.w);
}

// ---------------------------------------------------------------------------
// K2: GEMM1 via tf32 mma.sync.  h = silu([node|edge_sum] @ W1 + b1)
// BM=128 BN=128 BK=32, 256 thr (8 warps, 2m x 4n, warp tile 64x32).
// smem holds operands PRE-PERMUTED into m16n8k8 fragment layout:
//   sA[mtile(8)][kstep(4)][lane(32)][areg(4)]   (LDS.128 per frag)
//   sB[ntile(16)][kstep(4)][lane(32)][breg(2)]  (LDS.64 per frag)
// ---------------------------------------------------------------------------
__global__ __launch_bounds__(256) void gemm1_mma(const float* __restrict__ node,
                                                 const float* __restrict__ W1,
                                                 const float* __restrict__ b1) {
    __shared__ unsigned sA[8 * 4 * 32 * 4];   // 16 KB
    __shared__ unsigned sB[16 * 4 * 32 * 2];  // 16 KB

    int tid = threadIdx.x;
    int lane = tid & 31, wid = tid >> 5;
    int bx = blockIdx.x, by = blockIdx.y;
    int warp_m = wid >> 2, warp_n = wid & 3;
    int g = lane >> 2, tig = lane & 3;

    float acc[4][4][4] = {};
    float4 pa[4], pb[4];

    // ---- prefetch tile 0
    {
        const float* srcA = node;  // kt=0 < 16
#pragma unroll
        for (int l = 0; l < 4; ++l) {
            int idx = tid + l * 256;
            int m = idx >> 3, kq = idx & 7;
            int grow = by * 128 + m;
            pa[l] = (grow < NNODES)
                ? *reinterpret_cast<const float4*>(srcA + (size_t)grow * D + kq * 4)
                : make_float4(0.f, 0.f, 0.f, 0.f);
        }
#pragma unroll
        for (int l = 0; l < 4; ++l) {
            int idx = tid + l * 256;
            int k = idx >> 5, nq = idx & 31;
            pb[l] = *reinterpret_cast<const float4*>(W1 + (size_t)k * D + bx * 128 + nq * 4);
        }
    }

    for (int kt = 0; kt < 32; ++kt) {
        // ---- stage (permute + tf32 cvt) into smem
#pragma unroll
        for (int l = 0; l < 4; ++l) {
            int idx = tid + l * 256;
            int m = idx >> 3, kq = idx & 7;
            int mtile = m >> 4, gg = m & 7, hi_m = (m >> 3) & 1;
            int kstep = kq >> 1, hi_k = kq & 1;
            unsigned base = ((mtile * 4 + kstep) * 32) * 4 + hi_m + 2 * hi_k;
            const float* pv = &pa[l].x;
#pragma unroll
            for (int q = 0; q < 4; ++q)
                sA[base + (4 * gg + q) * 4] = tf32_of(pv[q]);
        }
#pragma unroll
        for (int l = 0; l < 4; ++l) {
            int idx = tid + l * 256;
            int k = idx >> 5, nq = idx & 31;
            int kstep = k >> 3, tg = k & 3, hi_k = (k >> 2) & 1;
            const float* pv = &pb[l].x;
#pragma unroll
            for (int q = 0; q < 4; ++q) {
                int n = nq * 4 + q;
                int ntile = n >> 3, gg = n & 7;
                sB[((ntile * 4 + kstep) * 32 + 4 * gg + tg) * 2 + hi_k] = tf32_of(pv[q]);
            }
        }
        __syncthreads();

        // ---- prefetch next tile (overlaps with mma)
        if (kt < 31) {
            int ktn = kt + 1;
            const float* srcA = (ktn < 16) ? node : g_edge_sum;
            int kbase = (ktn & 15) * 32;
#pragma unroll
            for (int l = 0; l < 4; ++l) {
                int idx = tid + l * 256;
                int m = idx >> 3, kq = idx & 7;
                int grow = by * 128 + m;
                pa[l] = (grow < NNODES)
                    ? *reinterpret_cast<const float4*>(srcA + (size_t)grow * D + kbase + kq * 4)
                    : make_float4(0.f, 0.f, 0.f, 0.f);
            }
#pragma unroll
            for (int l = 0; l < 4; ++l) {
                int idx = tid + l * 256;
                int k = idx >> 5, nq = idx & 31;
                pb[l] = *reinterpret_cast<const float4*>(
                    W1 + (size_t)(ktn * 32 + k) * D + bx * 128 + nq * 4);
            }
        }

        // ---- tensor-core compute
#pragma unroll
        for (int kstep = 0; kstep < 4; ++kstep) {
            uint4 a[4];
            uint2 b[4];
#pragma unroll
            for (int i = 0; i < 4; ++i)
                a[i] = *reinterpret_cast<const uint4*>(
                    &sA[(((warp_m * 4 + i) * 4 + kstep) * 32 + lane) * 4]);
#pragma unroll
            for (int j = 0; j < 4; ++j)
                b[j] = *reinterpret_cast<const uint2*>(
                    &sB[(((warp_n * 4 + j) * 4 + kstep) * 32 + lane) * 2]);
#pragma unroll
            for (int i = 0; i < 4; ++i)
#pragma unroll
                for (int j = 0; j < 4; ++j)
                    mma_tf32(acc[i][j], a[i], b[j]);
        }
        __syncthreads();
    }

    // ---- epilogue: bias + silu -> g_h (rows padded to MPAD, no write guard)
#pragma unroll
    for (int i = 0; i < 4; ++i) {
        int r0 = by * 128 + warp_m * 64 + i * 16 + g;
#pragma unroll
        for (int j = 0; j < 4; ++j) {
            int c0 = bx * 128 + warp_n * 32 + j * 8 + tig * 2;
            float bb0 = __ldg(&b1[c0]), bb1 = __ldg(&b1[c0 + 1]);
            float v0 = acc[i][j][0] + bb0;
            float v1 = acc[i][j][1] + bb1;
            float v2 = acc[i][j][2] + bb0;
            float v3 = acc[i][j][3] + bb1;
            v0 = v0 / (1.f + __expf(-v0));
            v1 = v1 / (1.f + __expf(-v1));
            v2 = v2 / (1.f + __expf(-v2));
            v3 = v3 / (1.f + __expf(-v3));
            *reinterpret_cast<float2*>(&g_h[(size_t)r0 * D + c0]) = make_float2(v0, v1);
            *reinterpret_cast<float2*>(&g_h[(size_t)(r0 + 8) * D + c0]) = make_float2(v2, v3);
        }
    }
}

// ---------------------------------------------------------------------------
// K3: GEMM2 + bias + LayerNorm fused, tf32 mma.
// BM=32 BN=512 (full rows per block -> in-block LN), BK=16.
// 8 warps, each warp 32x64 (mtiles=2, ntiles=8).
// ---------------------------------------------------------------------------
__global__ __launch_bounds__(256) void gemm2_ln_mma(const float* __restrict__ W2,
                                                    const float* __restrict__ b2,
                                                    const float* __restrict__ gamma,
                                                    const float* __restrict__ beta,
                                                    float* __restrict__ out) {
    __shared__ unsigned sA[2 * 2 * 32 * 4];    // 2 KB
    __shared__ unsigned sB[64 * 2 * 32 * 2];   // 32 KB
    __shared__ float mean_s[32], rstd_s[32];

    int tid = threadIdx.x;
    int lane = tid & 31, wid = tid >> 5;   // wid = warp_n (0..7)
    int bm = blockIdx.x;
    int g = lane >> 2, tig = lane & 3;

    float acc[2][8][4] = {};

    for (int kt = 0; kt < 32; ++kt) {
        // ---- stage A (32 x 16)
        if (tid < 128) {
            int m = tid >> 2, kq = tid & 3;
            float4 v = *reinterpret_cast<const float4*>(
                g_h + (size_t)(bm * 32 + m) * D + kt * 16 + kq * 4);
            int mtile = m >> 4, gg = m & 7, hi_m = (m >> 3) & 1;
            int kstep = kq >> 1, hi_k = kq & 1;
            unsigned base = ((mtile * 2 + kstep) * 32) * 4 + hi_m + 2 * hi_k;
            const float* pv = &v.x;
#pragma unroll
            for (int q = 0; q < 4; ++q)
                sA[base + (4 * gg + q) * 4] = tf32_of(pv[q]);
        }
        // ---- stage B (16 x 512)
#pragma unroll
        for (int l = 0; l < 8; ++l) {
            int idx = tid + l * 256;
            int k = idx >> 7, nq = idx & 127;
            float4 v = *reinterpret_cast<const float4*>(
                W2 + (size_t)(kt * 16 + k) * D + nq * 4);
            int kstep = k >> 3, tg = k & 3, hi_k = (k >> 2) & 1;
            const float* pv = &v.x;
#pragma unroll
            for (int q = 0; q < 4; ++q) {
                int n = nq * 4 + q;
                int ntile = n >> 3, gg = n & 7;
                sB[((ntile * 2 + kstep) * 32 + 4 * gg + tg) * 2 + hi_k] = tf32_of(pv[q]);
            }
        }
        __syncthreads();

#pragma unroll
        for (int kstep = 0; kstep < 2; ++kstep) {
            uint4 a[2];
            uint2 b[8];
#pragma unroll
            for (int i = 0; i < 2; ++i)
                a[i] = *reinterpret_cast<const uint4*>(
                    &sA[((i * 2 + kstep) * 32 + lane) * 4]);
#pragma unroll
            for (int j = 0; j < 8; ++j)
                b[j] = *reinterpret_cast<const uint2*>(
                    &sB[(((wid * 8 + j) * 2 + kstep) * 32 + lane) * 2]);
#pragma unroll
            for (int i = 0; i < 2; ++i)
#pragma unroll
                for (int j = 0; j < 8; ++j)
                    mma_tf32(acc[i][j], a[i], b[j]);
        }
        __syncthreads();
    }

    // ---- bias + per-row partial sums (rows owned: i*16 + hi*8 + g)
    float rsum[4] = {0.f, 0.f, 0.f, 0.f};
    float rsq[4]  = {0.f, 0.f, 0.f, 0.f};
#pragma unroll
    for (int i = 0; i < 2; ++i)
#pragma unroll
        for (int j = 0; j < 8; ++j) {
            int c0 = wid * 64 + j * 8 + tig * 2;
            float bb0 = __ldg(&b2[c0]), bb1 = __ldg(&b2[c0 + 1]);
            float v0 = acc[i][j][0] + bb0;
            float v1 = acc[i][j][1] + bb1;
            float v2 = acc[i][j][2] + bb0;
            float v3 = acc[i][j][3] + bb1;
            acc[i][j][0] = v0; acc[i][j][1] = v1;
            acc[i][j][2] = v2; acc[i][j][3] = v3;
            rsum[i * 2 + 0] += v0 + v1;
            rsq [i * 2 + 0] += v0 * v0 + v1 * v1;
            rsum[i * 2 + 1] += v2 + v3;
            rsq [i * 2 + 1] += v2 * v2 + v3 * v3;
        }

    // reduce over the 4 tig lanes (covers this warp's 64 cols)
#pragma unroll
    for (int h = 0; h < 4; ++h) {
        rsum[h] += __shfl_xor_sync(0xffffffffu, rsum[h], 1);
        rsum[h] += __shfl_xor_sync(0xffffffffu, rsum[h], 2);
        rsq[h]  += __shfl_xor_sync(0xffffffffu, rsq[h], 1);
        rsq[h]  += __shfl_xor_sync(0xffffffffu, rsq[h], 2);
    }

    // cross-warp reduction via smem (reuse sA; all smem reads done)
    float* red = reinterpret_cast<float*>(sA);  // [0..255]=sum, [256..511]=sq
    if (tig == 0) {
#pragma unroll
        for (int h = 0; h < 4; ++h) {
            int row = (h >> 1) * 16 + (h & 1) * 8 + g;
            red[row * 8 + wid] = rsum[h];
            red[256 + row * 8 + wid] = rsq[h];
        }
    }
    __syncthreads();
    if (tid < 32) {
        float s = 0.f, q = 0.f;
#pragma unroll
        for (int w = 0; w < 8; ++w) {
            s += red[tid * 8 + w];
            q += red[256 + tid * 8 + w];
        }
        float mean = s * (1.0f / 512.0f);
        float var = q * (1.0f / 512.0f) - mean * mean;
        mean_s[tid] = mean;
        rstd_s[tid] = rsqrtf(var + 1e-5f);
    }
    __syncthreads();

    // ---- normalize + affine + store
#pragma unroll
    for (int i = 0; i < 2; ++i)
#pragma unroll
        for (int hi = 0; hi < 2; ++hi) {
            int row = i * 16 + hi * 8 + g;
            int grow = bm * 32 + row;
            if (grow < NNODES) {
                float mean = mean_s[row], rstd = rstd_s[row];
#pragma unroll
                for (int j = 0; j < 8; ++j) {
                    int c0 = wid * 64 + j * 8 + tig * 2;
                    float ga0 = __ldg(&gamma[c0]), ga1 = __ldg(&gamma[c0 + 1]);
                    float be0 = __ldg(&beta[c0]),  be1 = __ldg(&beta[c0 + 1]);
                    float y0 = (acc[i][j][hi * 2 + 0] - mean) * rstd * ga0 + be0;
                    float y1 = (acc[i][j][hi * 2 + 1] - mean) * rstd * ga1 + be1;
                    *reinterpret_cast<float2*>(&out[(size_t)grow * D + c0]) =
                        make_float2(y0, y1);
                }
            }
        }
}

// ---------------------------------------------------------------------------
extern "C" void kernel_launch(void* const* d_in, const int* in_sizes, int n_in,
                              void* d_out, int out_size) {
    const float* node       = (const float*)d_in[0];
    const int*   edge_index = (const int*)  d_in[1];
    const float* edge_attr  = (const float*)d_in[2];
    const float* W1         = (const float*)d_in[3];
    const float* b1         = (const float*)d_in[4];
    const float* W2         = (const float*)d_in[5];
    const float* b2         = (const float*)d_in[6];
    const float* gamma      = (const float*)d_in[7];
    const float* beta       = (const float*)d_in[8];
    float* out = (float*)d_out;

    size_t n4 = (size_t)NNODES * D / 4;
    zero_kernel<<<(unsigned)((n4 + 255) / 256), 256>>>();
    scatter_kernel<<<NEDGES, 128>>>(edge_attr, edge_index);

    dim3 g1(4, (NNODES + 127) / 128);
    gemm1_mma<<<g1, 256>>>(node, W1, b1);

    gemm2_ln_mma<<<(NNODES + 31) / 32, 256>>>(W2, b2, gamma, beta, out);
}

// round 3
// speedup vs baseline: 2.6274x; 2.6274x over previous
#include <cuda_runtime.h>
#include <math.h>

#define NNODES 40962
#define NEDGES 327680
#define D 512
#define MPAD 41088  // 321*128 row padding

// Scratch (device globals: no allocations allowed)
__device__ float g_edge_sum[(size_t)NNODES * D];   // ~84 MB
__device__ float g_h[(size_t)MPAD * D];            // ~84 MB

__device__ __forceinline__ unsigned tf32_of(float f) {
    unsigned r;
    asm("cvt.rna.tf32.f32 %0, %1;" : "=r"(r) : "f"(f));
    return r;
}
__device__ __forceinline__ uint4 cvt4(float4 v) {
    return make_uint4(tf32_of(v.x), tf32_of(v.y), tf32_of(v.z), tf32_of(v.w));
}
__device__ __forceinline__ void mma_tf32(float* c, const unsigned* a, const unsigned* b) {
    asm volatile(
        "mma.sync.aligned.m16n8k8.row.col.f32.tf32.tf32.f32 "
        "{%0,%1,%2,%3}, {%4,%5,%6,%7}, {%8,%9}, {%0,%1,%2,%3};\n"
        : "+f"(c[0]), "+f"(c[1]), "+f"(c[2]), "+f"(c[3])
        : "r"(a[0]), "r"(a[1]), "r"(a[2]), "r"(a[3]), "r"(b[0]), "r"(b[1]));
}

// ---------------------------------------------------------------------------
__global__ void zero_kernel() {
    size_t i = (size_t)blockIdx.x * blockDim.x + threadIdx.x;
    size_t n4 = (size_t)NNODES * D / 4;
    if (i < n4) reinterpret_cast<float4*>(g_edge_sum)[i] = make_float4(0.f, 0.f, 0.f, 0.f);
}

__global__ void scatter_kernel(const float* __restrict__ edge_attr,
                               const int* __restrict__ edge_index) {
    int e = blockIdx.x;
    int t = threadIdx.x;
    int r = __ldg(&edge_index[NEDGES + e]);
    float4 v = *reinterpret_cast<const float4*>(edge_attr + (size_t)e * D + t * 4);
    float* dst = g_edge_sum + (size_t)r * D + t * 4;
    atomicAdd(dst + 0, v.x);
    atomicAdd(dst + 1, v.y);
    atomicAdd(dst + 2, v.z);
    atomicAdd(dst + 3, v.w);
}

// ---------------------------------------------------------------------------
// GEMM1: h = silu([node|edge_sum] @ W1 + b1)   M=40962 K=1024 N=512
// BM=128 BN=128 BK=16, 256 thr, warps 2m x 4n (warp tile 64x32).
// Padded-row smem (A stride 20, B stride 136): conflict-free frag LDS.32,
// staging is pure STS.128. Double buffered, reg prefetch.
// ---------------------------------------------------------------------------
#define G1_AS 20
#define G1_BS 136
__global__ __launch_bounds__(256, 2) void gemm1_mma(const float* __restrict__ node,
                                                    const float* __restrict__ W1,
                                                    const float* __restrict__ b1) {
    __shared__ unsigned sA[2][128 * G1_AS];  // 20 KB
    __shared__ unsigned sB[2][16 * G1_BS];   // 17 KB
    int tid = threadIdx.x, lane = tid & 31, wid = tid >> 5;
    int warp_m = wid >> 2, warp_n = wid & 3;
    int g = lane >> 2, tig = lane & 3;
    int bx = blockIdx.x, by = blockIdx.y;

    float acc[4][4][4] = {};
    float4 pa[2], pb[2];

    // ---- prefetch + stage kt=0
#pragma unroll
    for (int l = 0; l < 2; ++l) {
        int s = tid + l * 256, m = s >> 2, kg = s & 3;
        int grow = by * 128 + m;
        pa[l] = (grow < NNODES)
            ? *reinterpret_cast<const float4*>(node + (size_t)grow * D + kg * 4)
            : make_float4(0.f, 0.f, 0.f, 0.f);
    }
#pragma unroll
    for (int l = 0; l < 2; ++l) {
        int s = tid + l * 256, k = s >> 5, ng = s & 31;
        pb[l] = *reinterpret_cast<const float4*>(W1 + (size_t)k * D + bx * 128 + ng * 4);
    }
#pragma unroll
    for (int l = 0; l < 2; ++l) {
        int s = tid + l * 256, m = s >> 2, kg = s & 3;
        *reinterpret_cast<uint4*>(&sA[0][m * G1_AS + kg * 4]) = cvt4(pa[l]);
    }
#pragma unroll
    for (int l = 0; l < 2; ++l) {
        int s = tid + l * 256, k = s >> 5, ng = s & 31;
        *reinterpret_cast<uint4*>(&sB[0][k * G1_BS + ng * 4]) = cvt4(pb[l]);
    }
    __syncthreads();

    for (int kt = 0; kt < 64; ++kt) {
        int cur = kt & 1, nxt = cur ^ 1;
        if (kt < 63) {
            int ktn = kt + 1;
            const float* srcA = (ktn < 32) ? node : g_edge_sum;
            int kbase = (ktn & 31) * 16;
#pragma unroll
            for (int l = 0; l < 2; ++l) {
                int s = tid + l * 256, m = s >> 2, kg = s & 3;
                int grow = by * 128 + m;
                pa[l] = (grow < NNODES)
                    ? *reinterpret_cast<const float4*>(srcA + (size_t)grow * D + kbase + kg * 4)
                    : make_float4(0.f, 0.f, 0.f, 0.f);
            }
#pragma unroll
            for (int l = 0; l < 2; ++l) {
                int s = tid + l * 256, k = s >> 5, ng = s & 31;
                pb[l] = *reinterpret_cast<const float4*>(
                    W1 + (size_t)(ktn * 16 + k) * D + bx * 128 + ng * 4);
            }
        }
#pragma unroll
        for (int ks = 0; ks < 2; ++ks) {
            unsigned a[4][4], b[4][2];
#pragma unroll
            for (int i = 0; i < 4; ++i) {
                int base = (warp_m * 64 + i * 16 + g) * G1_AS + ks * 8 + tig;
                a[i][0] = sA[cur][base];
                a[i][1] = sA[cur][base + 8 * G1_AS];
                a[i][2] = sA[cur][base + 4];
                a[i][3] = sA[cur][base + 8 * G1_AS + 4];
            }
#pragma unroll
            for (int j = 0; j < 4; ++j) {
                int bb = (ks * 8 + tig) * G1_BS + warp_n * 32 + j * 8 + g;
                b[j][0] = sB[cur][bb];
                b[j][1] = sB[cur][bb + 4 * G1_BS];
            }
#pragma unroll
            for (int i = 0; i < 4; ++i)
#pragma unroll
                for (int j = 0; j < 4; ++j)
                    mma_tf32(acc[i][j], a[i], b[j]);
        }
        if (kt < 63) {
#pragma unroll
            for (int l = 0; l < 2; ++l) {
                int s = tid + l * 256, m = s >> 2, kg = s & 3;
                *reinterpret_cast<uint4*>(&sA[nxt][m * G1_AS + kg * 4]) = cvt4(pa[l]);
            }
#pragma unroll
            for (int l = 0; l < 2; ++l) {
                int s = tid + l * 256, k = s >> 5, ng = s & 31;
                *reinterpret_cast<uint4*>(&sB[nxt][k * G1_BS + ng * 4]) = cvt4(pb[l]);
            }
        }
        __syncthreads();
    }

    // ---- epilogue: bias + silu -> g_h (rows < MPAD, no guard)
#pragma unroll
    for (int i = 0; i < 4; ++i) {
        int r0 = by * 128 + warp_m * 64 + i * 16 + g;
#pragma unroll
        for (int j = 0; j < 4; ++j) {
            int c0 = bx * 128 + warp_n * 32 + j * 8 + tig * 2;
            float bb0 = __ldg(&b1[c0]), bb1 = __ldg(&b1[c0 + 1]);
            float v0 = acc[i][j][0] + bb0;
            float v1 = acc[i][j][1] + bb1;
            float v2 = acc[i][j][2] + bb0;
            float v3 = acc[i][j][3] + bb1;
            v0 = v0 / (1.f + __expf(-v0));
            v1 = v1 / (1.f + __expf(-v1));
            v2 = v2 / (1.f + __expf(-v2));
            v3 = v3 / (1.f + __expf(-v3));
            *reinterpret_cast<float2*>(&g_h[(size_t)r0 * D + c0]) = make_float2(v0, v1);
            *reinterpret_cast<float2*>(&g_h[(size_t)(r0 + 8) * D + c0]) = make_float2(v2, v3);
        }
    }
}

// ---------------------------------------------------------------------------
// GEMM2 + bias + LayerNorm fused.  BM=64 BN=512 (full rows) BK=8.
// 512 thr, 16 warps (2m x 8n), warp tile 32x64.
// ---------------------------------------------------------------------------
#define G2_AS 12
#define G2_BS 520
__global__ __launch_bounds__(512) void gemm2_ln_mma(const float* __restrict__ W2,
                                                    const float* __restrict__ b2,
                                                    const float* __restrict__ gamma,
                                                    const float* __restrict__ beta,
                                                    float* __restrict__ out) {
    __shared__ unsigned sA[2][64 * G2_AS];   // 6 KB
    __shared__ unsigned sB[2][8 * G2_BS];    // 32.5 KB
    __shared__ float mean_s[64], rstd_s[64];
    int tid = threadIdx.x, lane = tid & 31, wid = tid >> 5;
    int warp_m = wid >> 3, warp_n = wid & 7;
    int g = lane >> 2, tig = lane & 3;
    int bm = blockIdx.x;

    float acc[2][8][4] = {};
    float4 pa, pb[2];

    // ---- prefetch + stage kt=0
    if (tid < 128) {
        int m = tid >> 1, kg = tid & 1;
        pa = *reinterpret_cast<const float4*>(g_h + (size_t)(bm * 64 + m) * D + kg * 4);
    }
#pragma unroll
    for (int l = 0; l < 2; ++l) {
        int s = tid + l * 512, k = s >> 7, ng = s & 127;
        pb[l] = *reinterpret_cast<const float4*>(W2 + (size_t)k * D + ng * 4);
    }
    if (tid < 128) {
        int m = tid >> 1, kg = tid & 1;
        *reinterpret_cast<uint4*>(&sA[0][m * G2_AS + kg * 4]) = cvt4(pa);
    }
#pragma unroll
    for (int l = 0; l < 2; ++l) {
        int s = tid + l * 512, k = s >> 7, ng = s & 127;
        *reinterpret_cast<uint4*>(&sB[0][k * G2_BS + ng * 4]) = cvt4(pb[l]);
    }
    __syncthreads();

    for (int kt = 0; kt < 64; ++kt) {
        int cur = kt & 1, nxt = cur ^ 1;
        if (kt < 63) {
            int ktn = kt + 1;
            if (tid < 128) {
                int m = tid >> 1, kg = tid & 1;
                pa = *reinterpret_cast<const float4*>(
                    g_h + (size_t)(bm * 64 + m) * D + ktn * 8 + kg * 4);
            }
#pragma unroll
            for (int l = 0; l < 2; ++l) {
                int s = tid + l * 512, k = s >> 7, ng = s & 127;
                pb[l] = *reinterpret_cast<const float4*>(
                    W2 + (size_t)(ktn * 8 + k) * D + ng * 4);
            }
        }
        {
            unsigned a[2][4], b[8][2];
#pragma unroll
            for (int i = 0; i < 2; ++i) {
                int base = (warp_m * 32 + i * 16 + g) * G2_AS + tig;
                a[i][0] = sA[cur][base];
                a[i][1] = sA[cur][base + 8 * G2_AS];
                a[i][2] = sA[cur][base + 4];
                a[i][3] = sA[cur][base + 8 * G2_AS + 4];
            }
#pragma unroll
            for (int j = 0; j < 8; ++j) {
                int bb = tig * G2_BS + warp_n * 64 + j * 8 + g;
                b[j][0] = sB[cur][bb];
                b[j][1] = sB[cur][bb + 4 * G2_BS];
            }
#pragma unroll
            for (int i = 0; i < 2; ++i)
#pragma unroll
                for (int j = 0; j < 8; ++j)
                    mma_tf32(acc[i][j], a[i], b[j]);
        }
        if (kt < 63) {
            if (tid < 128) {
                int m = tid >> 1, kg = tid & 1;
                *reinterpret_cast<uint4*>(&sA[nxt][m * G2_AS + kg * 4]) = cvt4(pa);
            }
#pragma unroll
            for (int l = 0; l < 2; ++l) {
                int s = tid + l * 512, k = s >> 7, ng = s & 127;
                *reinterpret_cast<uint4*>(&sB[nxt][k * G2_BS + ng * 4]) = cvt4(pb[l]);
            }
        }
        __syncthreads();
    }

    // ---- bias + per-row partial sums (row slots h = i*2 + hi)
    float rsum[4] = {0.f, 0.f, 0.f, 0.f};
    float rsq[4]  = {0.f, 0.f, 0.f, 0.f};
#pragma unroll
    for (int i = 0; i < 2; ++i)
#pragma unroll
        for (int j = 0; j < 8; ++j) {
            int c0 = warp_n * 64 + j * 8 + tig * 2;
            float bb0 = __ldg(&b2[c0]), bb1 = __ldg(&b2[c0 + 1]);
            float v0 = acc[i][j][0] + bb0;
            float v1 = acc[i][j][1] + bb1;
            float v2 = acc[i][j][2] + bb0;
            float v3 = acc[i][j][3] + bb1;
            acc[i][j][0] = v0; acc[i][j][1] = v1;
            acc[i][j][2] = v2; acc[i][j][3] = v3;
            rsum[i * 2 + 0] += v0 + v1;
            rsq [i * 2 + 0] += v0 * v0 + v1 * v1;
            rsum[i * 2 + 1] += v2 + v3;
            rsq [i * 2 + 1] += v2 * v2 + v3 * v3;
        }
#pragma unroll
    for (int h = 0; h < 4; ++h) {
        rsum[h] += __shfl_xor_sync(0xffffffffu, rsum[h], 1);
        rsum[h] += __shfl_xor_sync(0xffffffffu, rsum[h], 2);
        rsq[h]  += __shfl_xor_sync(0xffffffffu, rsq[h], 1);
        rsq[h]  += __shfl_xor_sync(0xffffffffu, rsq[h], 2);
    }
    // cross-warp: red over the 8 warp_n groups (smem reads all done + synced)
    float* red = reinterpret_cast<float*>(sA);  // 1024 floats needed, 3072 avail
    if (tig == 0) {
#pragma unroll
        for (int h = 0; h < 4; ++h) {
            int row = warp_m * 32 + (h >> 1) * 16 + (h & 1) * 8 + g;
            red[row * 8 + warp_n] = rsum[h];
            red[512 + row * 8 + warp_n] = rsq[h];
        }
    }
    __syncthreads();
    if (tid < 64) {
        float s = 0.f, q = 0.f;
#pragma unroll
        for (int w = 0; w < 8; ++w) {
            s += red[tid * 8 + w];
            q += red[512 + tid * 8 + w];
        }
        float mean = s * (1.0f / 512.0f);
        float var = q * (1.0f / 512.0f) - mean * mean;
        mean_s[tid] = mean;
        rstd_s[tid] = rsqrtf(var + 1e-5f);
    }
    __syncthreads();

    // ---- normalize + affine + store
#pragma unroll
    for (int i = 0; i < 2; ++i)
#pragma unroll
        for (int hi = 0; hi < 2; ++hi) {
            int row = warp_m * 32 + i * 16 + hi * 8 + g;
            int grow = bm * 64 + row;
            if (grow < NNODES) {
                float mean = mean_s[row], rstd = rstd_s[row];
#pragma unroll
                for (int j = 0; j < 8; ++j) {
                    int c0 = warp_n * 64 + j * 8 + tig * 2;
                    float ga0 = __ldg(&gamma[c0]), ga1 = __ldg(&gamma[c0 + 1]);
                    float be0 = __ldg(&beta[c0]),  be1 = __ldg(&beta[c0 + 1]);
                    float y0 = (acc[i][j][hi * 2 + 0] - mean) * rstd * ga0 + be0;
                    float y1 = (acc[i][j][hi * 2 + 1] - mean) * rstd * ga1 + be1;
                    *reinterpret_cast<float2*>(&out[(size_t)grow * D + c0]) =
                        make_float2(y0, y1);
                }
            }
        }
}

// ---------------------------------------------------------------------------
extern "C" void kernel_launch(void* const* d_in, const int* in_sizes, int n_in,
                              void* d_out, int out_size) {
    const float* node       = (const float*)d_in[0];
    const int*   edge_index = (const int*)  d_in[1];
    const float* edge_attr  = (const float*)d_in[2];
    const float* W1         = (const float*)d_in[3];
    const float* b1         = (const float*)d_in[4];
    const float* W2         = (const float*)d_in[5];
    const float* b2         = (const float*)d_in[6];
    const float* gamma      = (const float*)d_in[7];
    const float* beta       = (const float*)d_in[8];
    float* out = (float*)d_out;

    size_t n4 = (size_t)NNODES * D / 4;
    zero_kernel<<<(unsigned)((n4 + 255) / 256), 256>>>();
    scatter_kernel<<<NEDGES, 128>>>(edge_attr, edge_index);

    dim3 g1(4, (NNODES + 127) / 128);
    gemm1_mma<<<g1, 256>>>(node, W1, b1);

    gemm2_ln_mma<<<(NNODES + 63) / 64, 512>>>(W2, b2, gamma, beta, out);
}

// round 6
// speedup vs baseline: 3.0072x; 1.1446x over previous
#include <cuda_runtime.h>
#include <math.h>

#define NNODES 40962
#define NEDGES 327680
#define D 512
#define K1 1024
#define MPAD 41088  // 321*128

// Scratch (device globals; no allocations allowed)
__device__ float g_edge_sum[(size_t)NNODES * D];   // 84 MB
__device__ float g_x[(size_t)MPAD * K1];           // 168 MB, tf32-rounded [node|edge_sum]
__device__ float g_h[(size_t)MPAD * D];            // 84 MB, tf32-rounded
__device__ float g_w1[(size_t)K1 * D];             // tf32-rounded W1
__device__ float g_w2[(size_t)D * D];              // tf32-rounded W2

__device__ __forceinline__ unsigned tf32_of(float f) {
    unsigned r;
    asm("cvt.rna.tf32.f32 %0, %1;" : "=r"(r) : "f"(f));
    return r;
}
__device__ __forceinline__ float4 rnd4(float4 v) {
    v.x = __uint_as_float(tf32_of(v.x));
    v.y = __uint_as_float(tf32_of(v.y));
    v.z = __uint_as_float(tf32_of(v.z));
    v.w = __uint_as_float(tf32_of(v.w));
    return v;
}
__device__ __forceinline__ void mma_tf32(float* c, const unsigned* a, const unsigned* b) {
    asm volatile(
        "mma.sync.aligned.m16n8k8.row.col.f32.tf32.tf32.f32 "
        "{%0,%1,%2,%3}, {%4,%5,%6,%7}, {%8,%9}, {%0,%1,%2,%3};\n"
        : "+f"(c[0]), "+f"(c[1]), "+f"(c[2]), "+f"(c[3])
        : "r"(a[0]), "r"(a[1]), "r"(a[2]), "r"(a[3]), "r"(b[0]), "r"(b[1]));
}
__device__ __forceinline__ void cp16(float* sdst, const float* gsrc) {
    unsigned sa = (unsigned)__cvta_generic_to_shared(sdst);
    asm volatile("cp.async.cg.shared.global [%0], [%1], 16;\n" :: "r"(sa), "l"(gsrc));
}
#define CP_COMMIT() asm volatile("cp.async.commit_group;\n")
#define CP_WAIT2()  asm volatile("cp.async.wait_group 2;\n")

// ---------------------------------------------------------------------------
__global__ void zero_kernel() {
    size_t i = (size_t)blockIdx.x * blockDim.x + threadIdx.x;
    size_t n4 = (size_t)NNODES * D / 4;
    if (i < n4) reinterpret_cast<float4*>(g_edge_sum)[i] = make_float4(0.f, 0.f, 0.f, 0.f);
}

__global__ void scatter_kernel(const float* __restrict__ edge_attr,
                               const int* __restrict__ edge_index) {
    int e = blockIdx.x;
    int t = threadIdx.x;
    int r = __ldg(&edge_index[NEDGES + e]);
    float4 v = *reinterpret_cast<const float4*>(edge_attr + (size_t)e * D + t * 4);
    float* dst = g_edge_sum + (size_t)r * D + t * 4;
    atomicAdd(dst + 0, v.x);
    atomicAdd(dst + 1, v.y);
    atomicAdd(dst + 2, v.z);
    atomicAdd(dst + 3, v.w);
}

// weights -> tf32
__global__ void convw_kernel(const float* __restrict__ W1, const float* __restrict__ W2) {
    int i = blockIdx.x * 256 + threadIdx.x;  // float4 index
    if (i < 131072) {
        reinterpret_cast<float4*>(g_w1)[i] =
            rnd4(reinterpret_cast<const float4*>(W1)[i]);
    } else if (i < 196608) {
        int j = i - 131072;
        reinterpret_cast<float4*>(g_w2)[j] =
            rnd4(reinterpret_cast<const float4*>(W2)[j]);
    }
}

// g_x[r] = tf32([node[r] | edge_sum[r]]), zero pad rows
__global__ void pack_kernel(const float* __restrict__ node) {
    int r = blockIdx.x;          // 0..MPAD-1
    int c = threadIdx.x * 4;     // 0..1020
    float4 v = make_float4(0.f, 0.f, 0.f, 0.f);
    if (r < NNODES) {
        v = (c < D)
            ? *reinterpret_cast<const float4*>(node + (size_t)r * D + c)
            : *reinterpret_cast<const float4*>(g_edge_sum + (size_t)r * D + (c - D));
    }
    *reinterpret_cast<float4*>(g_x + (size_t)r * K1 + c) = rnd4(v);
}

// ---------------------------------------------------------------------------
// GEMM1: h = silu(g_x @ g_w1 + b1)   M=MPAD K=1024 N=512
// BM=128 BN=128 BK=16, 256 thr, warps 2m x 4n. cp.async 4-stage pipeline.
// ---------------------------------------------------------------------------
#define G1_AS 20
#define G1_BS 136
#define G1_ASZ (128 * G1_AS)
#define G1_BSZ (16 * G1_BS)
__global__ __launch_bounds__(256, 2) void gemm1_mma(const float* __restrict__ b1) {
    extern __shared__ float smem[];
    float* sA = smem;                 // 4 stages * G1_ASZ
    float* sB = smem + 4 * G1_ASZ;    // 4 stages * G1_BSZ

    int tid = threadIdx.x, lane = tid & 31, wid = tid >> 5;
    int warp_m = wid >> 2, warp_n = wid & 3;
    int g = lane >> 2, tig = lane & 3;
    int bx = blockIdx.x, by = blockIdx.y;

    // per-thread load coordinates
    int am0 = tid >> 2, akg = (tid & 3) * 4;          // A chunk 0: row am0, col akg
    int bk0 = tid >> 5, bng = (tid & 31) * 4;         // B chunk 0: row bk0, col bng
    const float* gA = g_x + (size_t)(by * 128) * K1;
    const float* gB = g_w1 + (size_t)(bx * 128);

    float acc[4][4][4] = {};

#define G1_ISSUE(kt, st)                                                        \
    {                                                                           \
        cp16(&sA[(st) * G1_ASZ + am0 * G1_AS + akg],                            \
             gA + (size_t)am0 * K1 + (kt) * 16 + akg);                          \
        cp16(&sA[(st) * G1_ASZ + (am0 + 64) * G1_AS + akg],                     \
             gA + (size_t)(am0 + 64) * K1 + (kt) * 16 + akg);                   \
        cp16(&sB[(st) * G1_BSZ + bk0 * G1_BS + bng],                            \
             gB + (size_t)((kt) * 16 + bk0) * D + bng);                         \
        cp16(&sB[(st) * G1_BSZ + (bk0 + 8) * G1_BS + bng],                      \
             gB + (size_t)((kt) * 16 + bk0 + 8) * D + bng);                     \
        CP_COMMIT();                                                            \
    }

    G1_ISSUE(0, 0);
    G1_ISSUE(1, 1);
    G1_ISSUE(2, 2);

    for (int kt = 0; kt < 64; ++kt) {
        CP_WAIT2();
        __syncthreads();
        int cur = kt & 3;
        const float* cA = &sA[cur * G1_ASZ];
        const float* cB = &sB[cur * G1_BSZ];
#pragma unroll
        for (int ks = 0; ks < 2; ++ks) {
            unsigned a[4][4], b[4][2];
#pragma unroll
            for (int i = 0; i < 4; ++i) {
                int base = (warp_m * 64 + i * 16 + g) * G1_AS + ks * 8 + tig;
                a[i][0] = __float_as_uint(cA[base]);
                a[i][1] = __float_as_uint(cA[base + 8 * G1_AS]);
                a[i][2] = __float_as_uint(cA[base + 4]);
                a[i][3] = __float_as_uint(cA[base + 8 * G1_AS + 4]);
            }
#pragma unroll
            for (int j = 0; j < 4; ++j) {
                int bb = (ks * 8 + tig) * G1_BS + warp_n * 32 + j * 8 + g;
                b[j][0] = __float_as_uint(cB[bb]);
                b[j][1] = __float_as_uint(cB[bb + 4 * G1_BS]);
            }
#pragma unroll
            for (int i = 0; i < 4; ++i)
#pragma unroll
                for (int j = 0; j < 4; ++j)
                    mma_tf32(acc[i][j], a[i], b[j]);
        }
        if (kt + 3 < 64) {
            G1_ISSUE(kt + 3, (kt + 3) & 3);
        } else {
            CP_COMMIT();  // keep group count invariant
        }
    }

    // epilogue: bias + silu, tf32-round, store
#pragma unroll
    for (int i = 0; i < 4; ++i) {
        int r0 = by * 128 + warp_m * 64 + i * 16 + g;
#pragma unroll
        for (int j = 0; j < 4; ++j) {
            int c0 = bx * 128 + warp_n * 32 + j * 8 + tig * 2;
            float bb0 = __ldg(&b1[c0]), bb1 = __ldg(&b1[c0 + 1]);
            float v0 = acc[i][j][0] + bb0;
            float v1 = acc[i][j][1] + bb1;
            float v2 = acc[i][j][2] + bb0;
            float v3 = acc[i][j][3] + bb1;
            v0 = v0 / (1.f + __expf(-v0));
            v1 = v1 / (1.f + __expf(-v1));
            v2 = v2 / (1.f + __expf(-v2));
            v3 = v3 / (1.f + __expf(-v3));
            *reinterpret_cast<float2*>(&g_h[(size_t)r0 * D + c0]) =
                make_float2(__uint_as_float(tf32_of(v0)), __uint_as_float(tf32_of(v1)));
            *reinterpret_cast<float2*>(&g_h[(size_t)(r0 + 8) * D + c0]) =
                make_float2(__uint_as_float(tf32_of(v2)), __uint_as_float(tf32_of(v3)));
        }
    }
}

// ---------------------------------------------------------------------------
// GEMM2 + bias + LayerNorm.  BM=64 BN=512 (full rows) BK=8.
// 512 thr, 16 warps (2m x 8n). cp.async 4-stage.
// ---------------------------------------------------------------------------
#define G2_AS 12
#define G2_BS 520
#define G2_ASZ (64 * G2_AS)
#define G2_BSZ (8 * G2_BS)
__global__ __launch_bounds__(512, 1) void gemm2_ln_mma(const float* __restrict__ b2,
                                                       const float* __restrict__ gamma,
                                                       const float* __restrict__ beta,
                                                       float* __restrict__ out) {
    extern __shared__ float smem[];
    float* sA = smem;                 // 4 * G2_ASZ
    float* sB = smem + 4 * G2_ASZ;    // 4 * G2_BSZ
    __shared__ float mean_s[64], rstd_s[64];

    int tid = threadIdx.x, lane = tid & 31, wid = tid >> 5;
    int warp_m = wid >> 3, warp_n = wid & 7;
    int g = lane >> 2, tig = lane & 3;
    int bm = blockIdx.x;

    int am0 = tid >> 1, akg = (tid & 1) * 4;      // valid when tid<128
    int bk0 = tid >> 7, bng = (tid & 127) * 4;
    const float* gA = g_h + (size_t)(bm * 64) * D;

    float acc[2][8][4] = {};

#define G2_ISSUE(kt, st)                                                        \
    {                                                                           \
        if (tid < 128)                                                          \
            cp16(&sA[(st) * G2_ASZ + am0 * G2_AS + akg],                        \
                 gA + (size_t)am0 * D + (kt) * 8 + akg);                        \
        cp16(&sB[(st) * G2_BSZ + bk0 * G2_BS + bng],                            \
             g_w2 + (size_t)((kt) * 8 + bk0) * D + bng);                        \
        cp16(&sB[(st) * G2_BSZ + (bk0 + 4) * G2_BS + bng],                      \
             g_w2 + (size_t)((kt) * 8 + bk0 + 4) * D + bng);                    \
        CP_COMMIT();                                                            \
    }

    G2_ISSUE(0, 0);
    G2_ISSUE(1, 1);
    G2_ISSUE(2, 2);

    for (int kt = 0; kt < 64; ++kt) {
        CP_WAIT2();
        __syncthreads();
        int cur = kt & 3;
        const float* cA = &sA[cur * G2_ASZ];
        const float* cB = &sB[cur * G2_BSZ];
        {
            unsigned a[2][4], b[8][2];
#pragma unroll
            for (int i = 0; i < 2; ++i) {
                int base = (warp_m * 32 + i * 16 + g) * G2_AS + tig;
                a[i][0] = __float_as_uint(cA[base]);
                a[i][1] = __float_as_uint(cA[base + 8 * G2_AS]);
                a[i][2] = __float_as_uint(cA[base + 4]);
                a[i][3] = __float_as_uint(cA[base + 8 * G2_AS + 4]);
            }
#pragma unroll
            for (int j = 0; j < 8; ++j) {
                int bb = tig * G2_BS + warp_n * 64 + j * 8 + g;
                b[j][0] = __float_as_uint(cB[bb]);
                b[j][1] = __float_as_uint(cB[bb + 4 * G2_BS]);
            }
#pragma unroll
            for (int i = 0; i < 2; ++i)
#pragma unroll
                for (int j = 0; j < 8; ++j)
                    mma_tf32(acc[i][j], a[i], b[j]);
        }
        if (kt + 3 < 64) {
            G2_ISSUE(kt + 3, (kt + 3) & 3);
        } else {
            CP_COMMIT();
        }
    }

    // bias + per-row partial sums
    float rsum[4] = {0.f, 0.f, 0.f, 0.f};
    float rsq[4]  = {0.f, 0.f, 0.f, 0.f};
#pragma unroll
    for (int i = 0; i < 2; ++i)
#pragma unroll
        for (int j = 0; j < 8; ++j) {
            int c0 = warp_n * 64 + j * 8 + tig * 2;
            float bb0 = __ldg(&b2[c0]), bb1 = __ldg(&b2[c0 + 1]);
            float v0 = acc[i][j][0] + bb0;
            float v1 = acc[i][j][1] + bb1;
            float v2 = acc[i][j][2] + bb0;
            float v3 = acc[i][j][3] + bb1;
            acc[i][j][0] = v0; acc[i][j][1] = v1;
            acc[i][j][2] = v2; acc[i][j][3] = v3;
            rsum[i * 2 + 0] += v0 + v1;
            rsq [i * 2 + 0] += v0 * v0 + v1 * v1;
            rsum[i * 2 + 1] += v2 + v3;
            rsq [i * 2 + 1] += v2 * v2 + v3 * v3;
        }
#pragma unroll
    for (int h = 0; h < 4; ++h) {
        rsum[h] += __shfl_xor_sync(0xffffffffu, rsum[h], 1);
        rsum[h] += __shfl_xor_sync(0xffffffffu, rsum[h], 2);
        rsq[h]  += __shfl_xor_sync(0xffffffffu, rsq[h], 1);
        rsq[h]  += __shfl_xor_sync(0xffffffffu, rsq[h], 2);
    }
    __syncthreads();  // all mainloop smem reads done before reuse
    float* red = sB;  // need 1024 floats
    if (tig == 0) {
#pragma unroll
        for (int h = 0; h < 4; ++h) {
            int row = warp_m * 32 + (h >> 1) * 16 + (h & 1) * 8 + g;
            red[row * 8 + warp_n] = rsum[h];
            red[512 + row * 8 + warp_n] = rsq[h];
        }
    }
    __syncthreads();
    if (tid < 64) {
        float s = 0.f, q = 0.f;
#pragma unroll
        for (int w = 0; w < 8; ++w) {
            s += red[tid * 8 + w];
            q += red[512 + tid * 8 + w];
        }
        float mean = s * (1.0f / 512.0f);
        float var = q * (1.0f / 512.0f) - mean * mean;
        mean_s[tid] = mean;
        rstd_s[tid] = rsqrtf(var + 1e-5f);
    }
    __syncthreads();

#pragma unroll
    for (int i = 0; i < 2; ++i)
#pragma unroll
        for (int hi = 0; hi < 2; ++hi) {
            int row = warp_m * 32 + i * 16 + hi * 8 + g;
            int grow = bm * 64 + row;
            if (grow < NNODES) {
                float mean = mean_s[row], rstd = rstd_s[row];
#pragma unroll
                for (int j = 0; j < 8; ++j) {
                    int c0 = warp_n * 64 + j * 8 + tig * 2;
                    float ga0 = __ldg(&gamma[c0]), ga1 = __ldg(&gamma[c0 + 1]);
                    float be0 = __ldg(&beta[c0]),  be1 = __ldg(&beta[c0 + 1]);
                    float y0 = (acc[i][j][hi * 2 + 0] - mean) * rstd * ga0 + be0;
                    float y1 = (acc[i][j][hi * 2 + 1] - mean) * rstd * ga1 + be1;
                    *reinterpret_cast<float2*>(&out[(size_t)grow * D + c0]) =
                        make_float2(y0, y1);
                }
            }
        }
}

// ---------------------------------------------------------------------------
extern "C" void kernel_launch(void* const* d_in, const int* in_sizes, int n_in,
                              void* d_out, int out_size) {
    const float* node       = (const float*)d_in[0];
    const int*   edge_index = (const int*)  d_in[1];
    const float* edge_attr  = (const float*)d_in[2];
    const float* W1         = (const float*)d_in[3];
    const float* b1         = (const float*)d_in[4];
    const float* W2         = (const float*)d_in[5];
    const float* b2         = (const float*)d_in[6];
    const float* gamma      = (const float*)d_in[7];
    const float* beta       = (const float*)d_in[8];
    float* out = (float*)d_out;

    int smem1 = 4 * (G1_ASZ + G1_BSZ) * sizeof(float);  // 75776 B
    int smem2 = 4 * (G2_ASZ + G2_BSZ) * sizeof(float);  // 78848 B
    cudaFuncSetAttribute(gemm1_mma,   cudaFuncAttributeMaxDynamicSharedMemorySize, smem1);
    cudaFuncSetAttribute(gemm2_ln_mma, cudaFuncAttributeMaxDynamicSharedMemorySize, smem2);

    size_t n4 = (size_t)NNODES * D / 4;
    zero_kernel<<<(unsigned)((n4 + 255) / 256), 256>>>();
    convw_kernel<<<768, 256>>>(W1, W2);
    scatter_kernel<<<NEDGES, 128>>>(edge_attr, edge_index);
    pack_kernel<<<MPAD, 256>>>(node);

    dim3 g1(4, MPAD / 128);
    gemm1_mma<<<g1, 256, smem1>>>(b1);

    gemm2_ln_mma<<<MPAD / 64, 512, smem2>>>(b2, gamma, beta, out);
}

// round 7
// speedup vs baseline: 3.9640x; 1.3182x over previous
#include <cuda_runtime.h>
#include <math.h>

#define NNODES 40962
#define NEDGES 327680
#define D 512
#define K1 1024
#define MPAD 41088  // 321*128

// Scratch (device globals; no allocations allowed)
__device__ float g_edge_sum[(size_t)NNODES * D];   // 84 MB
__device__ float g_x[(size_t)MPAD * K1];           // 168 MB, tf32-rounded [node|edge_sum]
__device__ float g_h[(size_t)MPAD * D];            // 84 MB, tf32-rounded
__device__ float g_w1[(size_t)K1 * D];             // tf32-rounded W1
__device__ float g_w2[(size_t)D * D];              // tf32-rounded W2

__device__ __forceinline__ unsigned tf32_of(float f) {
    unsigned r;
    asm("cvt.rna.tf32.f32 %0, %1;" : "=r"(r) : "f"(f));
    return r;
}
__device__ __forceinline__ float4 rnd4(float4 v) {
    v.x = __uint_as_float(tf32_of(v.x));
    v.y = __uint_as_float(tf32_of(v.y));
    v.z = __uint_as_float(tf32_of(v.z));
    v.w = __uint_as_float(tf32_of(v.w));
    return v;
}
__device__ __forceinline__ void mma_tf32(float* c, const unsigned* a, const unsigned* b) {
    asm volatile(
        "mma.sync.aligned.m16n8k8.row.col.f32.tf32.tf32.f32 "
        "{%0,%1,%2,%3}, {%4,%5,%6,%7}, {%8,%9}, {%0,%1,%2,%3};\n"
        : "+f"(c[0]), "+f"(c[1]), "+f"(c[2]), "+f"(c[3])
        : "r"(a[0]), "r"(a[1]), "r"(a[2]), "r"(a[3]), "r"(b[0]), "r"(b[1]));
}
__device__ __forceinline__ void cp16(float* sdst, const float* gsrc) {
    unsigned sa = (unsigned)__cvta_generic_to_shared(sdst);
    asm volatile("cp.async.cg.shared.global [%0], [%1], 16;\n" :: "r"(sa), "l"(gsrc));
}
#define CP_COMMIT() asm volatile("cp.async.commit_group;\n")
#define CP_WAIT2()  asm volatile("cp.async.wait_group 2;\n")

// ---------------------------------------------------------------------------
__global__ void zero_kernel() {
    size_t i = (size_t)blockIdx.x * blockDim.x + threadIdx.x;
    size_t n4 = (size_t)NNODES * D / 4;
    if (i < n4) reinterpret_cast<float4*>(g_edge_sum)[i] = make_float4(0.f, 0.f, 0.f, 0.f);
}

// ---------------------------------------------------------------------------
// Scatter-add with VECTORIZED reductions: red.global.add.v4.f32 (sm_90+).
// One 16B reduction per thread-item -> 4x fewer REDG ops than scalar atomicAdd.
// Flat index: 128 workers per edge, 256-thread blocks (2 edges/block).
// ---------------------------------------------------------------------------
__global__ __launch_bounds__(256) void scatter_kernel(const float* __restrict__ edge_attr,
                                                      const int* __restrict__ edge_index) {
    int idx = blockIdx.x * 256 + threadIdx.x;
    int e = idx >> 7;         // edge id
    int t = idx & 127;        // float4 slot within the 512-float row
    int r = __ldg(&edge_index[NEDGES + e]);  // receiver
    float4 v = *reinterpret_cast<const float4*>(edge_attr + (size_t)e * D + t * 4);
    float* dst = g_edge_sum + (size_t)r * D + t * 4;
    asm volatile("red.global.add.v4.f32 [%0], {%1,%2,%3,%4};\n"
                 :: "l"(dst), "f"(v.x), "f"(v.y), "f"(v.z), "f"(v.w)
                 : "memory");
}

// weights -> tf32
__global__ void convw_kernel(const float* __restrict__ W1, const float* __restrict__ W2) {
    int i = blockIdx.x * 256 + threadIdx.x;  // float4 index
    if (i < 131072) {
        reinterpret_cast<float4*>(g_w1)[i] =
            rnd4(reinterpret_cast<const float4*>(W1)[i]);
    } else if (i < 196608) {
        int j = i - 131072;
        reinterpret_cast<float4*>(g_w2)[j] =
            rnd4(reinterpret_cast<const float4*>(W2)[j]);
    }
}

// g_x[r] = tf32([node[r] | edge_sum[r]]), zero pad rows
__global__ void pack_kernel(const float* __restrict__ node) {
    int r = blockIdx.x;          // 0..MPAD-1
    int c = threadIdx.x * 4;     // 0..1020
    float4 v = make_float4(0.f, 0.f, 0.f, 0.f);
    if (r < NNODES) {
        v = (c < D)
            ? *reinterpret_cast<const float4*>(node + (size_t)r * D + c)
            : *reinterpret_cast<const float4*>(g_edge_sum + (size_t)r * D + (c - D));
    }
    *reinterpret_cast<float4*>(g_x + (size_t)r * K1 + c) = rnd4(v);
}

// ---------------------------------------------------------------------------
// GEMM1: h = silu(g_x @ g_w1 + b1)   M=MPAD K=1024 N=512
// BM=128 BN=128 BK=16, 256 thr, warps 2m x 4n. cp.async 4-stage pipeline.
// ---------------------------------------------------------------------------
#define G1_AS 20
#define G1_BS 136
#define G1_ASZ (128 * G1_AS)
#define G1_BSZ (16 * G1_BS)
__global__ __launch_bounds__(256, 2) void gemm1_mma(const float* __restrict__ b1) {
    extern __shared__ float smem[];
    float* sA = smem;                 // 4 stages * G1_ASZ
    float* sB = smem + 4 * G1_ASZ;    // 4 stages * G1_BSZ

    int tid = threadIdx.x, lane = tid & 31, wid = tid >> 5;
    int warp_m = wid >> 2, warp_n = wid & 3;
    int g = lane >> 2, tig = lane & 3;
    int bx = blockIdx.x, by = blockIdx.y;

    int am0 = tid >> 2, akg = (tid & 3) * 4;
    int bk0 = tid >> 5, bng = (tid & 31) * 4;
    const float* gA = g_x + (size_t)(by * 128) * K1;
    const float* gB = g_w1 + (size_t)(bx * 128);

    float acc[4][4][4] = {};

#define G1_ISSUE(kt, st)                                                        \
    {                                                                           \
        cp16(&sA[(st) * G1_ASZ + am0 * G1_AS + akg],                            \
             gA + (size_t)am0 * K1 + (kt) * 16 + akg);                          \
        cp16(&sA[(st) * G1_ASZ + (am0 + 64) * G1_AS + akg],                     \
             gA + (size_t)(am0 + 64) * K1 + (kt) * 16 + akg);                   \
        cp16(&sB[(st) * G1_BSZ + bk0 * G1_BS + bng],                            \
             gB + (size_t)((kt) * 16 + bk0) * D + bng);                         \
        cp16(&sB[(st) * G1_BSZ + (bk0 + 8) * G1_BS + bng],                      \
             gB + (size_t)((kt) * 16 + bk0 + 8) * D + bng);                     \
        CP_COMMIT();                                                            \
    }

    G1_ISSUE(0, 0);
    G1_ISSUE(1, 1);
    G1_ISSUE(2, 2);

    for (int kt = 0; kt < 64; ++kt) {
        CP_WAIT2();
        __syncthreads();
        int cur = kt & 3;
        const float* cA = &sA[cur * G1_ASZ];
        const float* cB = &sB[cur * G1_BSZ];
#pragma unroll
        for (int ks = 0; ks < 2; ++ks) {
            unsigned a[4][4], b[4][2];
#pragma unroll
            for (int i = 0; i < 4; ++i) {
                int base = (warp_m * 64 + i * 16 + g) * G1_AS + ks * 8 + tig;
                a[i][0] = __float_as_uint(cA[base]);
                a[i][1] = __float_as_uint(cA[base + 8 * G1_AS]);
                a[i][2] = __float_as_uint(cA[base + 4]);
                a[i][3] = __float_as_uint(cA[base + 8 * G1_AS + 4]);
            }
#pragma unroll
            for (int j = 0; j < 4; ++j) {
                int bb = (ks * 8 + tig) * G1_BS + warp_n * 32 + j * 8 + g;
                b[j][0] = __float_as_uint(cB[bb]);
                b[j][1] = __float_as_uint(cB[bb + 4 * G1_BS]);
            }
#pragma unroll
            for (int i = 0; i < 4; ++i)
#pragma unroll
                for (int j = 0; j < 4; ++j)
                    mma_tf32(acc[i][j], a[i], b[j]);
        }
        if (kt + 3 < 64) {
            G1_ISSUE(kt + 3, (kt + 3) & 3);
        } else {
            CP_COMMIT();
        }
    }

    // epilogue: bias + silu, tf32-round, store
#pragma unroll
    for (int i = 0; i < 4; ++i) {
        int r0 = by * 128 + warp_m * 64 + i * 16 + g;
#pragma unroll
        for (int j = 0; j < 4; ++j) {
            int c0 = bx * 128 + warp_n * 32 + j * 8 + tig * 2;
            float bb0 = __ldg(&b1[c0]), bb1 = __ldg(&b1[c0 + 1]);
            float v0 = acc[i][j][0] + bb0;
            float v1 = acc[i][j][1] + bb1;
            float v2 = acc[i][j][2] + bb0;
            float v3 = acc[i][j][3] + bb1;
            v0 = v0 / (1.f + __expf(-v0));
            v1 = v1 / (1.f + __expf(-v1));
            v2 = v2 / (1.f + __expf(-v2));
            v3 = v3 / (1.f + __expf(-v3));
            *reinterpret_cast<float2*>(&g_h[(size_t)r0 * D + c0]) =
                make_float2(__uint_as_float(tf32_of(v0)), __uint_as_float(tf32_of(v1)));
            *reinterpret_cast<float2*>(&g_h[(size_t)(r0 + 8) * D + c0]) =
                make_float2(__uint_as_float(tf32_of(v2)), __uint_as_float(tf32_of(v3)));
        }
    }
}

// ---------------------------------------------------------------------------
// GEMM2 + bias + LayerNorm.  BM=64 BN=512 (full rows) BK=8.
// 512 thr, 16 warps (2m x 8n). cp.async 4-stage.
// ---------------------------------------------------------------------------
#define G2_AS 12
#define G2_BS 520
#define G2_ASZ (64 * G2_AS)
#define G2_BSZ (8 * G2_BS)
__global__ __launch_bounds__(512, 1) void gemm2_ln_mma(const float* __restrict__ b2,
                                                       const float* __restrict__ gamma,
                                                       const float* __restrict__ beta,
                                                       float* __restrict__ out) {
    extern __shared__ float smem[];
    float* sA = smem;                 // 4 * G2_ASZ
    float* sB = smem + 4 * G2_ASZ;    // 4 * G2_BSZ
    __shared__ float mean_s[64], rstd_s[64];

    int tid = threadIdx.x, lane = tid & 31, wid = tid >> 5;
    int warp_m = wid >> 3, warp_n = wid & 7;
    int g = lane >> 2, tig = lane & 3;
    int bm = blockIdx.x;

    int am0 = tid >> 1, akg = (tid & 1) * 4;      // valid when tid<128
    int bk0 = tid >> 7, bng = (tid & 127) * 4;
    const float* gA = g_h + (size_t)(bm * 64) * D;

    float acc[2][8][4] = {};

#define G2_ISSUE(kt, st)                                                        \
    {                                                                           \
        if (tid < 128)                                                          \
            cp16(&sA[(st) * G2_ASZ + am0 * G2_AS + akg],                        \
                 gA + (size_t)am0 * D + (kt) * 8 + akg);                        \
        cp16(&sB[(st) * G2_BSZ + bk0 * G2_BS + bng],                            \
             g_w2 + (size_t)((kt) * 8 + bk0) * D + bng);                        \
        cp16(&sB[(st) * G2_BSZ + (bk0 + 4) * G2_BS + bng],                      \
             g_w2 + (size_t)((kt) * 8 + bk0 + 4) * D + bng);                    \
        CP_COMMIT();                                                            \
    }

    G2_ISSUE(0, 0);
    G2_ISSUE(1, 1);
    G2_ISSUE(2, 2);

    for (int kt = 0; kt < 64; ++kt) {
        CP_WAIT2();
        __syncthreads();
        int cur = kt & 3;
        const float* cA = &sA[cur * G2_ASZ];
        const float* cB = &sB[cur * G2_BSZ];
        {
            unsigned a[2][4], b[8][2];
#pragma unroll
            for (int i = 0; i < 2; ++i) {
                int base = (warp_m * 32 + i * 16 + g) * G2_AS + tig;
                a[i][0] = __float_as_uint(cA[base]);
                a[i][1] = __float_as_uint(cA[base + 8 * G2_AS]);
                a[i][2] = __float_as_uint(cA[base + 4]);
                a[i][3] = __float_as_uint(cA[base + 8 * G2_AS + 4]);
            }
#pragma unroll
            for (int j = 0; j < 8; ++j) {
                int bb = tig * G2_BS + warp_n * 64 + j * 8 + g;
                b[j][0] = __float_as_uint(cB[bb]);
                b[j][1] = __float_as_uint(cB[bb + 4 * G2_BS]);
            }
#pragma unroll
            for (int i = 0; i < 2; ++i)
#pragma unroll
                for (int j = 0; j < 8; ++j)
                    mma_tf32(acc[i][j], a[i], b[j]);
        }
        if (kt + 3 < 64) {
            G2_ISSUE(kt + 3, (kt + 3) & 3);
        } else {
            CP_COMMIT();
        }
    }

    // bias + per-row partial sums
    float rsum[4] = {0.f, 0.f, 0.f, 0.f};
    float rsq[4]  = {0.f, 0.f, 0.f, 0.f};
#pragma unroll
    for (int i = 0; i < 2; ++i)
#pragma unroll
        for (int j = 0; j < 8; ++j) {
            int c0 = warp_n * 64 + j * 8 + tig * 2;
            float bb0 = __ldg(&b2[c0]), bb1 = __ldg(&b2[c0 + 1]);
            float v0 = acc[i][j][0] + bb0;
            float v1 = acc[i][j][1] + bb1;
            float v2 = acc[i][j][2] + bb0;
            float v3 = acc[i][j][3] + bb1;
            acc[i][j][0] = v0; acc[i][j][1] = v1;
            acc[i][j][2] = v2; acc[i][j][3] = v3;
            rsum[i * 2 + 0] += v0 + v1;
            rsq [i * 2 + 0] += v0 * v0 + v1 * v1;
            rsum[i * 2 + 1] += v2 + v3;
            rsq [i * 2 + 1] += v2 * v2 + v3 * v3;
        }
#pragma unroll
    for (int h = 0; h < 4; ++h) {
        rsum[h] += __shfl_xor_sync(0xffffffffu, rsum[h], 1);
        rsum[h] += __shfl_xor_sync(0xffffffffu, rsum[h], 2);
        rsq[h]  += __shfl_xor_sync(0xffffffffu, rsq[h], 1);
        rsq[h]  += __shfl_xor_sync(0xffffffffu, rsq[h], 2);
    }
    __syncthreads();  // all mainloop smem reads done before reuse
    float* red = sB;  // need 1024 floats
    if (tig == 0) {
#pragma unroll
        for (int h = 0; h < 4; ++h) {
            int row = warp_m * 32 + (h >> 1) * 16 + (h & 1) * 8 + g;
            red[row * 8 + warp_n] = rsum[h];
            red[512 + row * 8 + warp_n] = rsq[h];
        }
    }
    __syncthreads();
    if (tid < 64) {
        float s = 0.f, q = 0.f;
#pragma unroll
        for (int w = 0; w < 8; ++w) {
            s += red[tid * 8 + w];
            q += red[512 + tid * 8 + w];
        }
        float mean = s * (1.0f / 512.0f);
        float var = q * (1.0f / 512.0f) - mean * mean;
        mean_s[tid] = mean;
        rstd_s[tid] = rsqrtf(var + 1e-5f);
    }
    __syncthreads();

#pragma unroll
    for (int i = 0; i < 2; ++i)
#pragma unroll
        for (int hi = 0; hi < 2; ++hi) {
            int row = warp_m * 32 + i * 16 + hi * 8 + g;
            int grow = bm * 64 + row;
            if (grow < NNODES) {
                float mean = mean_s[row], rstd = rstd_s[row];
#pragma unroll
                for (int j = 0; j < 8; ++j) {
                    int c0 = warp_n * 64 + j * 8 + tig * 2;
                    float ga0 = __ldg(&gamma[c0]), ga1 = __ldg(&gamma[c0 + 1]);
                    float be0 = __ldg(&beta[c0]),  be1 = __ldg(&beta[c0 + 1]);
                    float y0 = (acc[i][j][hi * 2 + 0] - mean) * rstd * ga0 + be0;
                    float y1 = (acc[i][j][hi * 2 + 1] - mean) * rstd * ga1 + be1;
                    *reinterpret_cast<float2*>(&out[(size_t)grow * D + c0]) =
                        make_float2(y0, y1);
                }
            }
        }
}

// ---------------------------------------------------------------------------
extern "C" void kernel_launch(void* const* d_in, const int* in_sizes, int n_in,
                              void* d_out, int out_size) {
    const float* node       = (const float*)d_in[0];
    const int*   edge_index = (const int*)  d_in[1];
    const float* edge_attr  = (const float*)d_in[2];
    const float* W1         = (const float*)d_in[3];
    const float* b1         = (const float*)d_in[4];
    const float* W2         = (const float*)d_in[5];
    const float* b2         = (const float*)d_in[6];
    const float* gamma      = (const float*)d_in[7];
    const float* beta       = (const float*)d_in[8];
    float* out = (float*)d_out;

    int smem1 = 4 * (G1_ASZ + G1_BSZ) * sizeof(float);  // 75776 B
    int smem2 = 4 * (G2_ASZ + G2_BSZ) * sizeof(float);  // 78848 B
    cudaFuncSetAttribute(gemm1_mma,    cudaFuncAttributeMaxDynamicSharedMemorySize, smem1);
    cudaFuncSetAttribute(gemm2_ln_mma, cudaFuncAttributeMaxDynamicSharedMemorySize, smem2);

    size_t n4 = (size_t)NNODES * D / 4;
    zero_kernel<<<(unsigned)((n4 + 255) / 256), 256>>>();
    convw_kernel<<<768, 256>>>(W1, W2);
    scatter_kernel<<<NEDGES * 128 / 256, 256>>>(edge_attr, edge_index);
    pack_kernel<<<MPAD, 256>>>(node);

    dim3 g1(4, MPAD / 128);
    gemm1_mma<<<g1, 256, smem1>>>(b1);

    gemm2_ln_mma<<<MPAD / 64, 512, smem2>>>(b2, gamma, beta, out);
}

// round 9
// speedup vs baseline: 5.2313x; 1.3197x over previous
#include <cuda_runtime.h>
#include <cuda_fp16.h>
#include <math.h>
#include <stdint.h>

#define NNODES 40962
#define NEDGES 327680
#define D 512
#define K1 1024
#define MPAD 41088  // 321*128

// Scratch (device globals; no allocations allowed)
__device__ float  g_edge_sum[(size_t)NNODES * D];   // 84 MB fp32 accum
__device__ __half g_x[(size_t)MPAD * K1];           // 84 MB  [node|edge_sum] fp16
__device__ __half g_h[(size_t)MPAD * D];            // 42 MB  hidden fp16
__device__ __half g_w1t[(size_t)D * K1];            // W1^T [n=512][k=1024] fp16
__device__ __half g_w2t[(size_t)D * D];             // W2^T [n=512][k=512]  fp16

__device__ __forceinline__ void mma_f16(float* c, const unsigned* a, const unsigned* b) {
    asm volatile(
        "mma.sync.aligned.m16n8k16.row.col.f32.f16.f16.f32 "
        "{%0,%1,%2,%3}, {%4,%5,%6,%7}, {%8,%9}, {%0,%1,%2,%3};\n"
        : "+f"(c[0]), "+f"(c[1]), "+f"(c[2]), "+f"(c[3])
        : "r"(a[0]), "r"(a[1]), "r"(a[2]), "r"(a[3]), "r"(b[0]), "r"(b[1]));
}
__device__ __forceinline__ void cp16(void* sdst, const void* gsrc) {
    unsigned sa = (unsigned)__cvta_generic_to_shared(sdst);
    asm volatile("cp.async.cg.shared.global [%0], [%1], 16;\n" :: "r"(sa), "l"(gsrc));
}
#define CP_COMMIT() asm volatile("cp.async.commit_group;\n")
#define CP_WAIT2()  asm volatile("cp.async.wait_group 2;\n")

__device__ __forceinline__ unsigned h2u(__half2 h) {
    return *reinterpret_cast<unsigned*>(&h);
}

// ---------------------------------------------------------------------------
__global__ void zero_kernel() {
    size_t i = (size_t)blockIdx.x * blockDim.x + threadIdx.x;
    size_t n4 = (size_t)NNODES * D / 4;
    if (i < n4) reinterpret_cast<float4*>(g_edge_sum)[i] = make_float4(0.f, 0.f, 0.f, 0.f);
}

// vectorized scatter: red.global.add.v4.f32
__global__ __launch_bounds__(256) void scatter_kernel(const float* __restrict__ edge_attr,
                                                      const int* __restrict__ edge_index) {
    int idx = blockIdx.x * 256 + threadIdx.x;
    int e = idx >> 7;
    int t = idx & 127;
    int r = __ldg(&edge_index[NEDGES + e]);
    float4 v = *reinterpret_cast<const float4*>(edge_attr + (size_t)e * D + t * 4);
    float* dst = g_edge_sum + (size_t)r * D + t * 4;
    asm volatile("red.global.add.v4.f32 [%0], {%1,%2,%3,%4};\n"
                 :: "l"(dst), "f"(v.x), "f"(v.y), "f"(v.z), "f"(v.w)
                 : "memory");
}

// W1 [k=1024][n=512] -> g_w1t [n][k] fp16
__global__ void convw1t_kernel(const float* __restrict__ W1) {
    __shared__ float t[32][33];
    int bx = blockIdx.x;   // k tile (32 tiles)
    int by = blockIdx.y;   // n tile (16 tiles)
    int x = threadIdx.x, y = threadIdx.y;  // 32 x 8
#pragma unroll
    for (int i = 0; i < 32; i += 8)
        t[y + i][x] = W1[(size_t)(bx * 32 + y + i) * D + by * 32 + x];
    __syncthreads();
#pragma unroll
    for (int i = 0; i < 32; i += 8)
        g_w1t[(size_t)(by * 32 + y + i) * K1 + bx * 32 + x] = __float2half_rn(t[x][y + i]);
}

// W2 [k=512][n=512] -> g_w2t [n][k] fp16
__global__ void convw2t_kernel(const float* __restrict__ W2) {
    __shared__ float t[32][33];
    int bx = blockIdx.x;   // k tile (16)
    int by = blockIdx.y;   // n tile (16)
    int x = threadIdx.x, y = threadIdx.y;
#pragma unroll
    for (int i = 0; i < 32; i += 8)
        t[y + i][x] = W2[(size_t)(bx * 32 + y + i) * D + by * 32 + x];
    __syncthreads();
#pragma unroll
    for (int i = 0; i < 32; i += 8)
        g_w2t[(size_t)(by * 32 + y + i) * D + bx * 32 + x] = __float2half_rn(t[x][y + i]);
}

// g_x[r] = fp16([node[r] | edge_sum[r]]), zero for pad rows
__global__ void pack_kernel(const float* __restrict__ node) {
    int r = blockIdx.x;
    int c = threadIdx.x * 4;
    float4 v = make_float4(0.f, 0.f, 0.f, 0.f);
    if (r < NNODES) {
        v = (c < D)
            ? *reinterpret_cast<const float4*>(node + (size_t)r * D + c)
            : *reinterpret_cast<const float4*>(g_edge_sum + (size_t)r * D + (c - D));
    }
    __half2 h01 = __floats2half2_rn(v.x, v.y);
    __half2 h23 = __floats2half2_rn(v.z, v.w);
    uint2 o = make_uint2(h2u(h01), h2u(h23));
    *reinterpret_cast<uint2*>(g_x + (size_t)r * K1 + c) = o;
}

// ---------------------------------------------------------------------------
// GEMM1: h = silu(g_x @ W1 + b1)   M=MPAD K=1024 N=512, fp16 mma m16n8k16.
// BM=128 BN=128 BK=32. 256 thr, 8 warps (2m x 4n), warp tile 64x32.
// A,B smem tiles: [128 rows][16 half2 words], word stride 20 (conflict-free).
// 4-stage cp.async.
// ---------------------------------------------------------------------------
#define G1_RS 20                  // row stride in 32-bit words
#define G1_TILE (128 * G1_RS)     // words per operand tile
#define G1_STW (2 * G1_TILE)      // words per stage (A+B)
__global__ __launch_bounds__(256, 2) void gemm1_f16(const float* __restrict__ b1) {
    extern __shared__ unsigned smw[];
    int tid = threadIdx.x, lane = tid & 31, wid = tid >> 5;
    int warp_m = wid >> 2, warp_n = wid & 3;
    int g = lane >> 2, tig = lane & 3;
    int bx = blockIdx.x, by = blockIdx.y;

    const __half* aSrc = g_x + (size_t)(by * 128) * K1;
    const __half* bSrc = g_w1t + (size_t)(bx * 128) * K1;

    float acc[4][4][4] = {};

#define G1_ISSUE(kt, st)                                                         \
    {                                                                            \
        unsigned* base = smw + (st) * G1_STW;                                    \
        _Pragma("unroll")                                                        \
        for (int t = 0; t < 2; ++t) {                                            \
            int idx = tid + t * 256;                                             \
            int row = idx >> 2, wq = (idx & 3) * 4;                              \
            cp16(base + row * G1_RS + wq,                                        \
                 aSrc + (size_t)row * K1 + (kt) * 32 + wq * 2);                  \
        }                                                                        \
        _Pragma("unroll")                                                        \
        for (int t = 0; t < 2; ++t) {                                            \
            int idx = tid + t * 256;                                             \
            int row = idx >> 2, wq = (idx & 3) * 4;                              \
            cp16(base + G1_TILE + row * G1_RS + wq,                              \
                 bSrc + (size_t)row * K1 + (kt) * 32 + wq * 2);                  \
        }                                                                        \
        CP_COMMIT();                                                             \
    }

    G1_ISSUE(0, 0);
    G1_ISSUE(1, 1);
    G1_ISSUE(2, 2);

    for (int kt = 0; kt < 32; ++kt) {
        CP_WAIT2();
        __syncthreads();
        const unsigned* cA = smw + (kt & 3) * G1_STW;
        const unsigned* cB = cA + G1_TILE;
#pragma unroll
        for (int ks = 0; ks < 2; ++ks) {
            unsigned a[4][4], b[4][2];
#pragma unroll
            for (int i = 0; i < 4; ++i) {
                int base = (warp_m * 64 + i * 16 + g) * G1_RS + ks * 8 + tig;
                a[i][0] = cA[base];
                a[i][1] = cA[base + 8 * G1_RS];
                a[i][2] = cA[base + 4];
                a[i][3] = cA[base + 8 * G1_RS + 4];
            }
#pragma unroll
            for (int j = 0; j < 4; ++j) {
                int nb = (warp_n * 32 + j * 8 + g) * G1_RS + ks * 8 + tig;
                b[j][0] = cB[nb];
                b[j][1] = cB[nb + 4];
            }
#pragma unroll
            for (int i = 0; i < 4; ++i)
#pragma unroll
                for (int j = 0; j < 4; ++j)
                    mma_f16(acc[i][j], a[i], b[j]);
        }
        if (kt + 3 < 32) {
            G1_ISSUE(kt + 3, (kt + 3) & 3);
        } else {
            CP_COMMIT();
        }
    }

    // epilogue: bias + silu -> fp16 g_h
#pragma unroll
    for (int i = 0; i < 4; ++i) {
        int r0 = by * 128 + warp_m * 64 + i * 16 + g;
#pragma unroll
        for (int j = 0; j < 4; ++j) {
            int c0 = bx * 128 + warp_n * 32 + j * 8 + tig * 2;
            float bb0 = __ldg(&b1[c0]), bb1 = __ldg(&b1[c0 + 1]);
            float v0 = acc[i][j][0] + bb0;
            float v1 = acc[i][j][1] + bb1;
            float v2 = acc[i][j][2] + bb0;
            float v3 = acc[i][j][3] + bb1;
            v0 = v0 / (1.f + __expf(-v0));
            v1 = v1 / (1.f + __expf(-v1));
            v2 = v2 / (1.f + __expf(-v2));
            v3 = v3 / (1.f + __expf(-v3));
            *reinterpret_cast<unsigned*>(&g_h[(size_t)r0 * D + c0]) =
                h2u(__floats2half2_rn(v0, v1));
            *reinterpret_cast<unsigned*>(&g_h[(size_t)(r0 + 8) * D + c0]) =
                h2u(__floats2half2_rn(v2, v3));
        }
    }
}

// ---------------------------------------------------------------------------
// GEMM2 + bias + LayerNorm fused.  BM=64 BN=512 (full rows) BK=32, fp16 mma.
// 512 thr, 16 warps (2m x 8n), warp tile 32x64. 4-stage cp.async.
// ---------------------------------------------------------------------------
#define G2_RS 20
#define G2_ATILE (64 * G2_RS)     // 1280 words
#define G2_BTILE (512 * G2_RS)    // 10240 words
#define G2_STW (G2_ATILE + G2_BTILE)
__global__ __launch_bounds__(512, 1) void gemm2_ln_f16(const float* __restrict__ b2,
                                                       const float* __restrict__ gamma,
                                                       const float* __restrict__ beta,
                                                       float* __restrict__ out) {
    extern __shared__ unsigned smw[];
    __shared__ float mean_s[64], rstd_s[64];

    int tid = threadIdx.x, lane = tid & 31, wid = tid >> 5;
    int warp_m = wid >> 3, warp_n = wid & 7;
    int g = lane >> 2, tig = lane & 3;
    int bm = blockIdx.x;

    const __half* aSrc = g_h + (size_t)(bm * 64) * D;

    float acc[2][8][4] = {};

#define G2_ISSUE(kt, st)                                                         \
    {                                                                            \
        unsigned* base = smw + (st) * G2_STW;                                    \
        if (tid < 256) {                                                         \
            int row = tid >> 2, wq = (tid & 3) * 4;                              \
            cp16(base + row * G2_RS + wq,                                        \
                 aSrc + (size_t)row * D + (kt) * 32 + wq * 2);                   \
        }                                                                        \
        _Pragma("unroll")                                                        \
        for (int t = 0; t < 4; ++t) {                                            \
            int idx = tid + t * 512;                                             \
            int row = idx >> 2, wq = (idx & 3) * 4;                              \
            cp16(base + G2_ATILE + row * G2_RS + wq,                             \
                 g_w2t + (size_t)row * D + (kt) * 32 + wq * 2);                  \
        }                                                                        \
        CP_COMMIT();                                                             \
    }

    G2_ISSUE(0, 0);
    G2_ISSUE(1, 1);
    G2_ISSUE(2, 2);

    for (int kt = 0; kt < 16; ++kt) {
        CP_WAIT2();
        __syncthreads();
        const unsigned* cA = smw + (kt & 3) * G2_STW;
        const unsigned* cB = cA + G2_ATILE;
#pragma unroll
        for (int ks = 0; ks < 2; ++ks) {
            unsigned a[2][4], b[8][2];
#pragma unroll
            for (int i = 0; i < 2; ++i) {
                int base = (warp_m * 32 + i * 16 + g) * G2_RS + ks * 8 + tig;
                a[i][0] = cA[base];
                a[i][1] = cA[base + 8 * G2_RS];
                a[i][2] = cA[base + 4];
                a[i][3] = cA[base + 8 * G2_RS + 4];
            }
#pragma unroll
            for (int j = 0; j < 8; ++j) {
                int nb = (warp_n * 64 + j * 8 + g) * G2_RS + ks * 8 + tig;
                b[j][0] = cB[nb];
                b[j][1] = cB[nb + 4];
            }
#pragma unroll
            for (int i = 0; i < 2; ++i)
#pragma unroll
                for (int j = 0; j < 8; ++j)
                    mma_f16(acc[i][j], a[i], b[j]);
        }
        if (kt + 3 < 16) {
            G2_ISSUE(kt + 3, (kt + 3) & 3);
        } else {
            CP_COMMIT();
        }
    }

    // bias + per-row partial sums
    float rsum[4] = {0.f, 0.f, 0.f, 0.f};
    float rsq[4]  = {0.f, 0.f, 0.f, 0.f};
#pragma unroll
    for (int i = 0; i < 2; ++i)
#pragma unroll
        for (int j = 0; j < 8; ++j) {
            int c0 = warp_n * 64 + j * 8 + tig * 2;
            float bb0 = __ldg(&b2[c0]), bb1 = __ldg(&b2[c0 + 1]);
            float v0 = acc[i][j][0] + bb0;
            float v1 = acc[i][j][1] + bb1;
            float v2 = acc[i][j][2] + bb0;
            float v3 = acc[i][j][3] + bb1;
            acc[i][j][0] = v0; acc[i][j][1] = v1;
            acc[i][j][2] = v2; acc[i][j][3] = v3;
            rsum[i * 2 + 0] += v0 + v1;
            rsq [i * 2 + 0] += v0 * v0 + v1 * v1;
            rsum[i * 2 + 1] += v2 + v3;
            rsq [i * 2 + 1] += v2 * v2 + v3 * v3;
        }
#pragma unroll
    for (int h = 0; h < 4; ++h) {
        rsum[h] += __shfl_xor_sync(0xffffffffu, rsum[h], 1);
        rsum[h] += __shfl_xor_sync(0xffffffffu, rsum[h], 2);
        rsq[h]  += __shfl_xor_sync(0xffffffffu, rsq[h], 1);
        rsq[h]  += __shfl_xor_sync(0xffffffffu, rsq[h], 2);
    }
    __syncthreads();  // mainloop smem reads done before reuse
    float* red = reinterpret_cast<float*>(smw);  // 1024 floats
    if (tig == 0) {
#pragma unroll
        for (int h = 0; h < 4; ++h) {
            int row = warp_m * 32 + (h >> 1) * 16 + (h & 1) * 8 + g;
            red[row * 8 + warp_n] = rsum[h];
            red[512 + row * 8 + warp_n] = rsq[h];
        }
    }
    __syncthreads();
    if (tid < 64) {
        float s = 0.f, q = 0.f;
#pragma unroll
        for (int w = 0; w < 8; ++w) {
            s += red[tid * 8 + w];
            q += red[512 + tid * 8 + w];
        }
        float mean = s * (1.0f / 512.0f);
        float var = q * (1.0f / 512.0f) - mean * mean;
        mean_s[tid] = mean;
        rstd_s[tid] = rsqrtf(var + 1e-5f);
    }
    __syncthreads();

#pragma unroll
    for (int i = 0; i < 2; ++i)
#pragma unroll
        for (int hi = 0; hi < 2; ++hi) {
            int row = warp_m * 32 + i * 16 + hi * 8 + g;
            int grow = bm * 64 + row;
            if (grow < NNODES) {
                float mean = mean_s[row], rstd = rstd_s[row];
#pragma unroll
                for (int j = 0; j < 8; ++j) {
                    int c0 = warp_n * 64 + j * 8 + tig * 2;
                    float ga0 = __ldg(&gamma[c0]), ga1 = __ldg(&gamma[c0 + 1]);
                    float be0 = __ldg(&beta[c0]),  be1 = __ldg(&beta[c0 + 1]);
                    float y0 = (acc[i][j][hi * 2 + 0] - mean) * rstd * ga0 + be0;
                    float y1 = (acc[i][j][hi * 2 + 1] - mean) * rstd * ga1 + be1;
                    *reinterpret_cast<float2*>(&out[(size_t)grow * D + c0]) =
                        make_float2(y0, y1);
                }
            }
        }
}

// ---------------------------------------------------------------------------
extern "C" void kernel_launch(void* const* d_in, const int* in_sizes, int n_in,
                              void* d_out, int out_size) {
    const float* node       = (const float*)d_in[0];
    const int*   edge_index = (const int*)  d_in[1];
    const float* edge_attr  = (const float*)d_in[2];
    const float* W1         = (const float*)d_in[3];
    const float* b1         = (const float*)d_in[4];
    const float* W2         = (const float*)d_in[5];
    const float* b2         = (const float*)d_in[6];
    const float* gamma      = (const float*)d_in[7];
    const float* beta       = (const float*)d_in[8];
    float* out = (float*)d_out;

    int smem1 = 4 * G1_STW * sizeof(unsigned);  // 81920 B
    int smem2 = 4 * G2_STW * sizeof(unsigned);  // 184320 B
    cudaFuncSetAttribute(gemm1_f16,    cudaFuncAttributeMaxDynamicSharedMemorySize, smem1);
    cudaFuncSetAttribute(gemm2_ln_f16, cudaFuncAttributeMaxDynamicSharedMemorySize, smem2);

    size_t n4 = (size_t)NNODES * D / 4;
    zero_kernel<<<(unsigned)((n4 + 255) / 256), 256>>>();
    convw1t_kernel<<<dim3(32, 16), dim3(32, 8)>>>(W1);
    convw2t_kernel<<<dim3(16, 16), dim3(32, 8)>>>(W2);
    scatter_kernel<<<NEDGES * 128 / 256, 256>>>(edge_attr, edge_index);
    pack_kernel<<<MPAD, 256>>>(node);

    dim3 g1(4, MPAD / 128);
    gemm1_f16<<<g1, 256, smem1>>>(b1);

    gemm2_ln_f16<<<MPAD / 64, 512, smem2>>>(b2, gamma, beta, out);
}

// round 11
// speedup vs baseline: 5.5466x; 1.0603x over previous
#include <cuda_runtime.h>
#include <cuda_fp16.h>
#include <math.h>
#include <stdint.h>

#define NNODES 40962
#define NEDGES 327680
#define D 512
#define K1 1024
#define MPAD 41088  // 321*128

// Scratch (device globals; no allocations allowed)
__device__ float  g_edge_sum[(size_t)NNODES * D];   // 84 MB fp32 accum
__device__ __half g_x[(size_t)MPAD * K1];           // 84 MB  [node|edge_sum] fp16
__device__ __half g_h[(size_t)MPAD * D];            // 42 MB  hidden fp16
__device__ __half g_w1t[(size_t)D * K1];            // W1^T [n=512][k=1024] fp16
__device__ __half g_w2t[(size_t)D * D];             // W2^T [n=512][k=512]  fp16

__device__ __forceinline__ void mma_f16(float* c, const unsigned* a, const unsigned* b) {
    asm volatile(
        "mma.sync.aligned.m16n8k16.row.col.f32.f16.f16.f32 "
        "{%0,%1,%2,%3}, {%4,%5,%6,%7}, {%8,%9}, {%0,%1,%2,%3};\n"
        : "+f"(c[0]), "+f"(c[1]), "+f"(c[2]), "+f"(c[3])
        : "r"(a[0]), "r"(a[1]), "r"(a[2]), "r"(a[3]), "r"(b[0]), "r"(b[1]));
}
__device__ __forceinline__ void cp16(void* sdst, const void* gsrc) {
    unsigned sa = (unsigned)__cvta_generic_to_shared(sdst);
    asm volatile("cp.async.cg.shared.global [%0], [%1], 16;\n" :: "r"(sa), "l"(gsrc));
}
#define CP_COMMIT() asm volatile("cp.async.commit_group;\n")
#define CP_WAIT2()  asm volatile("cp.async.wait_group 2;\n")

__device__ __forceinline__ unsigned h2u(__half2 h) {
    return *reinterpret_cast<unsigned*>(&h);
}

// ---------------------------------------------------------------------------
__global__ void zero_kernel() {
    size_t i = (size_t)blockIdx.x * blockDim.x + threadIdx.x;
    size_t n4 = (size_t)NNODES * D / 4;
    if (i < n4) reinterpret_cast<float4*>(g_edge_sum)[i] = make_float4(0.f, 0.f, 0.f, 0.f);
}

// Vectorized scatter. edge_attr is pure streaming traffic: load with the .cs
// (cache-streaming / evict-first) qualifier so the 84MB edge_sum RMW target
// stays L2-resident instead of being evicted by the 671MB stream.
__global__ __launch_bounds__(256) void scatter_kernel(const float* __restrict__ edge_attr,
                                                      const int* __restrict__ edge_index) {
    int idx = blockIdx.x * 256 + threadIdx.x;
    int e = idx >> 7;
    int t = idx & 127;
    int r = __ldg(&edge_index[NEDGES + e]);
    float4 v = __ldcs(reinterpret_cast<const float4*>(edge_attr + (size_t)e * D + t * 4));
    float* dst = g_edge_sum + (size_t)r * D + t * 4;
    asm volatile("red.global.add.v4.f32 [%0], {%1,%2,%3,%4};\n"
                 :: "l"(dst), "f"(v.x), "f"(v.y), "f"(v.z), "f"(v.w)
                 : "memory");
}

// W1 [k=1024][n=512] -> g_w1t [n][k] fp16
__global__ void convw1t_kernel(const float* __restrict__ W1) {
    __shared__ float t[32][33];
    int bx = blockIdx.x;   // k tile (32 tiles)
    int by = blockIdx.y;   // n tile (16 tiles)
    int x = threadIdx.x, y = threadIdx.y;  // 32 x 8
#pragma unroll
    for (int i = 0; i < 32; i += 8)
        t[y + i][x] = W1[(size_t)(bx * 32 + y + i) * D + by * 32 + x];
    __syncthreads();
#pragma unroll
    for (int i = 0; i < 32; i += 8)
        g_w1t[(size_t)(by * 32 + y + i) * K1 + bx * 32 + x] = __float2half_rn(t[x][y + i]);
}

// W2 [k=512][n=512] -> g_w2t [n][k] fp16
__global__ void convw2t_kernel(const float* __restrict__ W2) {
    __shared__ float t[32][33];
    int bx = blockIdx.x;   // k tile (16)
    int by = blockIdx.y;   // n tile (16)
    int x = threadIdx.x, y = threadIdx.y;
#pragma unroll
    for (int i = 0; i < 32; i += 8)
        t[y + i][x] = W2[(size_t)(bx * 32 + y + i) * D + by * 32 + x];
    __syncthreads();
#pragma unroll
    for (int i = 0; i < 32; i += 8)
        g_w2t[(size_t)(by * 32 + y + i) * D + bx * 32 + x] = __float2half_rn(t[x][y + i]);
}

// g_x[r] = fp16([node[r] | edge_sum[r]]), zero for pad rows
__global__ void pack_kernel(const float* __restrict__ node) {
    int r = blockIdx.x;
    int c = threadIdx.x * 4;
    float4 v = make_float4(0.f, 0.f, 0.f, 0.f);
    if (r < NNODES) {
        v = (c < D)
            ? *reinterpret_cast<const float4*>(node + (size_t)r * D + c)
            : *reinterpret_cast<const float4*>(g_edge_sum + (size_t)r * D + (c - D));
    }
    __half2 h01 = __floats2half2_rn(v.x, v.y);
    __half2 h23 = __floats2half2_rn(v.z, v.w);
    uint2 o = make_uint2(h2u(h01), h2u(h23));
    *reinterpret_cast<uint2*>(g_x + (size_t)r * K1 + c) = o;
}

// ---------------------------------------------------------------------------
// GEMM1: h = silu(g_x @ W1 + b1)   M=MPAD K=1024 N=512, fp16 mma m16n8k16.
// BM=128 BN=128 BK=32. 256 thr, 8 warps (2m x 4n), warp tile 64x32.
// A,B smem tiles: [128 rows][16 half2 words], word stride 20 (conflict-free).
// 4-stage cp.async.
// ---------------------------------------------------------------------------
#define G1_RS 20                  // row stride in 32-bit words
#define G1_TILE (128 * G1_RS)     // words per operand tile
#define G1_STW (2 * G1_TILE)      // words per stage (A+B)
__global__ __launch_bounds__(256, 2) void gemm1_f16(const float* __restrict__ b1) {
    extern __shared__ unsigned smw[];
    int tid = threadIdx.x, lane = tid & 31, wid = tid >> 5;
    int warp_m = wid >> 2, warp_n = wid & 3;
    int g = lane >> 2, tig = lane & 3;
    int bx = blockIdx.x, by = blockIdx.y;

    const __half* aSrc = g_x + (size_t)(by * 128) * K1;
    const __half* bSrc = g_w1t + (size_t)(bx * 128) * K1;

    float acc[4][4][4] = {};

#define G1_ISSUE(kt, st)                                                         \
    {                                                                            \
        unsigned* base = smw + (st) * G1_STW;                                    \
        _Pragma("unroll")                                                        \
        for (int t = 0; t < 2; ++t) {                                            \
            int idx = tid + t * 256;                                             \
            int row = idx >> 2, wq = (idx & 3) * 4;                              \
            cp16(base + row * G1_RS + wq,                                        \
                 aSrc + (size_t)row * K1 + (kt) * 32 + wq * 2);                  \
        }                                                                        \
        _Pragma("unroll")                                                        \
        for (int t = 0; t < 2; ++t) {                                            \
            int idx = tid + t * 256;                                             \
            int row = idx >> 2, wq = (idx & 3) * 4;                              \
            cp16(base + G1_TILE + row * G1_RS + wq,                              \
                 bSrc + (size_t)row * K1 + (kt) * 32 + wq * 2);                  \
        }                                                                        \
        CP_COMMIT();                                                             \
    }

    G1_ISSUE(0, 0);
    G1_ISSUE(1, 1);
    G1_ISSUE(2, 2);

    for (int kt = 0; kt < 32; ++kt) {
        CP_WAIT2();
        __syncthreads();
        const unsigned* cA = smw + (kt & 3) * G1_STW;
        const unsigned* cB = cA + G1_TILE;
#pragma unroll
        for (int ks = 0; ks < 2; ++ks) {
            unsigned a[4][4], b[4][2];
#pragma unroll
            for (int i = 0; i < 4; ++i) {
                int base = (warp_m * 64 + i * 16 + g) * G1_RS + ks * 8 + tig;
                a[i][0] = cA[base];
                a[i][1] = cA[base + 8 * G1_RS];
                a[i][2] = cA[base + 4];
                a[i][3] = cA[base + 8 * G1_RS + 4];
            }
#pragma unroll
            for (int j = 0; j < 4; ++j) {
                int nb = (warp_n * 32 + j * 8 + g) * G1_RS + ks * 8 + tig;
                b[j][0] = cB[nb];
                b[j][1] = cB[nb + 4];
            }
#pragma unroll
            for (int i = 0; i < 4; ++i)
#pragma unroll
                for (int j = 0; j < 4; ++j)
                    mma_f16(acc[i][j], a[i], b[j]);
        }
        if (kt + 3 < 32) {
            G1_ISSUE(kt + 3, (kt + 3) & 3);
        } else {
            CP_COMMIT();
        }
    }

    // epilogue: bias + silu -> fp16 g_h
#pragma unroll
    for (int i = 0; i < 4; ++i) {
        int r0 = by * 128 + warp_m * 64 + i * 16 + g;
#pragma unroll
        for (int j = 0; j < 4; ++j) {
            int c0 = bx * 128 + warp_n * 32 + j * 8 + tig * 2;
            float bb0 = __ldg(&b1[c0]), bb1 = __ldg(&b1[c0 + 1]);
            float v0 = acc[i][j][0] + bb0;
            float v1 = acc[i][j][1] + bb1;
            float v2 = acc[i][j][2] + bb0;
            float v3 = acc[i][j][3] + bb1;
            v0 = v0 / (1.f + __expf(-v0));
            v1 = v1 / (1.f + __expf(-v1));
            v2 = v2 / (1.f + __expf(-v2));
            v3 = v3 / (1.f + __expf(-v3));
            *reinterpret_cast<unsigned*>(&g_h[(size_t)r0 * D + c0]) =
                h2u(__floats2half2_rn(v0, v1));
            *reinterpret_cast<unsigned*>(&g_h[(size_t)(r0 + 8) * D + c0]) =
                h2u(__floats2half2_rn(v2, v3));
        }
    }
}

// ---------------------------------------------------------------------------
// GEMM2 + bias + LayerNorm fused.  BM=64 BN=512 (full rows) BK=32, fp16 mma.
// 512 thr, 16 warps (2m x 8n), warp tile 32x64. 4-stage cp.async.
// ---------------------------------------------------------------------------
#define G2_RS 20
#define G2_ATILE (64 * G2_RS)     // 1280 words
#define G2_BTILE (512 * G2_RS)    // 10240 words
#define G2_STW (G2_ATILE + G2_BTILE)
__global__ __launch_bounds__(512, 1) void gemm2_ln_f16(const float* __restrict__ b2,
                                                       const float* __restrict__ gamma,
                                                       const float* __restrict__ beta,
                                                       float* __restrict__ out) {
    extern __shared__ unsigned smw[];
    __shared__ float mean_s[64], rstd_s[64];

    int tid = threadIdx.x, lane = tid & 31, wid = tid >> 5;
    int warp_m = wid >> 3, warp_n = wid & 7;
    int g = lane >> 2, tig = lane & 3;
    int bm = blockIdx.x;

    const __half* aSrc = g_h + (size_t)(bm * 64) * D;

    float acc[2][8][4] = {};

#define G2_ISSUE(kt, st)                                                         \
    {                                                                            \
        unsigned* base = smw + (st) * G2_STW;                                    \
        if (tid < 256) {                                                         \
            int row = tid >> 2, wq = (tid & 3) * 4;                              \
            cp16(base + row * G2_RS + wq,                                        \
                 aSrc + (size_t)row * D + (kt) * 32 + wq * 2);                   \
        }                                                                        \
        _Pragma("unroll")                                                        \
        for (int t = 0; t < 4; ++t) {                                            \
            int idx = tid + t * 512;                                             \
            int row = idx >> 2, wq = (idx & 3) * 4;                              \
            cp16(base + G2_ATILE + row * G2_RS + wq,                             \
                 g_w2t + (size_t)row * D + (kt) * 32 + wq * 2);                  \
        }                                                                        \
        CP_COMMIT();                                                             \
    }

    G2_ISSUE(0, 0);
    G2_ISSUE(1, 1);
    G2_ISSUE(2, 2);

    for (int kt = 0; kt < 16; ++kt) {
        CP_WAIT2();
        __syncthreads();
        const unsigned* cA = smw + (kt & 3) * G2_STW;
        const unsigned* cB = cA + G2_ATILE;
#pragma unroll
        for (int ks = 0; ks < 2; ++ks) {
            unsigned a[2][4], b[8][2];
#pragma unroll
            for (int i = 0; i < 2; ++i) {
                int base = (warp_m * 32 + i * 16 + g) * G2_RS + ks * 8 + tig;
                a[i][0] = cA[base];
                a[i][1] = cA[base + 8 * G2_RS];
                a[i][2] = cA[base + 4];
                a[i][3] = cA[base + 8 * G2_RS + 4];
            }
#pragma unroll
            for (int j = 0; j < 8; ++j) {
                int nb = (warp_n * 64 + j * 8 + g) * G2_RS + ks * 8 + tig;
                b[j][0] = cB[nb];
                b[j][1] = cB[nb + 4];
            }
#pragma unroll
            for (int i = 0; i < 2; ++i)
#pragma unroll
                for (int j = 0; j < 8; ++j)
                    mma_f16(acc[i][j], a[i], b[j]);
        }
        if (kt + 3 < 16) {
            G2_ISSUE(kt + 3, (kt + 3) & 3);
        } else {
            CP_COMMIT();
        }
    }

    // bias + per-row partial sums
    float rsum[4] = {0.f, 0.f, 0.f, 0.f};
    float rsq[4]  = {0.f, 0.f, 0.f, 0.f};
#pragma unroll
    for (int i = 0; i < 2; ++i)
#pragma unroll
        for (int j = 0; j < 8; ++j) {
            int c0 = warp_n * 64 + j * 8 + tig * 2;
            float bb0 = __ldg(&b2[c0]), bb1 = __ldg(&b2[c0 + 1]);
            float v0 = acc[i][j][0] + bb0;
            float v1 = acc[i][j][1] + bb1;
            float v2 = acc[i][j][2] + bb0;
            float v3 = acc[i][j][3] + bb1;
            acc[i][j][0] = v0; acc[i][j][1] = v1;
            acc[i][j][2] = v2; acc[i][j][3] = v3;
            rsum[i * 2 + 0] += v0 + v1;
            rsq [i * 2 + 0] += v0 * v0 + v1 * v1;
            rsum[i * 2 + 1] += v2 + v3;
            rsq [i * 2 + 1] += v2 * v2 + v3 * v3;
        }
#pragma unroll
    for (int h = 0; h < 4; ++h) {
        rsum[h] += __shfl_xor_sync(0xffffffffu, rsum[h], 1);
        rsum[h] += __shfl_xor_sync(0xffffffffu, rsum[h], 2);
        rsq[h]  += __shfl_xor_sync(0xffffffffu, rsq[h], 1);
        rsq[h]  += __shfl_xor_sync(0xffffffffu, rsq[h], 2);
    }
    __syncthreads();  // mainloop smem reads done before reuse
    float* red = reinterpret_cast<float*>(smw);  // 1024 floats
    if (tig == 0) {
#pragma unroll
        for (int h = 0; h < 4; ++h) {
            int row = warp_m * 32 + (h >> 1) * 16 + (h & 1) * 8 + g;
            red[row * 8 + warp_n] = rsum[h];
            red[512 + row * 8 + warp_n] = rsq[h];
        }
    }
    __syncthreads();
    if (tid < 64) {
        float s = 0.f, q = 0.f;
#pragma unroll
        for (int w = 0; w < 8; ++w) {
            s += red[tid * 8 + w];
            q += red[512 + tid * 8 + w];
        }
        float mean = s * (1.0f / 512.0f);
        float var = q * (1.0f / 512.0f) - mean * mean;
        mean_s[tid] = mean;
        rstd_s[tid] = rsqrtf(var + 1e-5f);
    }
    __syncthreads();

#pragma unroll
    for (int i = 0; i < 2; ++i)
#pragma unroll
        for (int hi = 0; hi < 2; ++hi) {
            int row = warp_m * 32 + i * 16 + hi * 8 + g;
            int grow = bm * 64 + row;
            if (grow < NNODES) {
                float mean = mean_s[row], rstd = rstd_s[row];
#pragma unroll
                for (int j = 0; j < 8; ++j) {
                    int c0 = warp_n * 64 + j * 8 + tig * 2;
                    float ga0 = __ldg(&gamma[c0]), ga1 = __ldg(&gamma[c0 + 1]);
                    float be0 = __ldg(&beta[c0]),  be1 = __ldg(&beta[c0 + 1]);
                    float y0 = (acc[i][j][hi * 2 + 0] - mean) * rstd * ga0 + be0;
                    float y1 = (acc[i][j][hi * 2 + 1] - mean) * rstd * ga1 + be1;
                    *reinterpret_cast<float2*>(&out[(size_t)grow * D + c0]) =
                        make_float2(y0, y1);
                }
            }
        }
}

// ---------------------------------------------------------------------------
extern "C" void kernel_launch(void* const* d_in, const int* in_sizes, int n_in,
                              void* d_out, int out_size) {
    const float* node       = (const float*)d_in[0];
    const int*   edge_index = (const int*)  d_in[1];
    const float* edge_attr  = (const float*)d_in[2];
    const float* W1         = (const float*)d_in[3];
    const float* b1         = (const float*)d_in[4];
    const float* W2         = (const float*)d_in[5];
    const float* b2         = (const float*)d_in[6];
    const float* gamma      = (const float*)d_in[7];
    const float* beta       = (const float*)d_in[8];
    float* out = (float*)d_out;

    int smem1 = 4 * G1_STW * sizeof(unsigned);  // 81920 B
    int smem2 = 4 * G2_STW * sizeof(unsigned);  // 184320 B
    cudaFuncSetAttribute(gemm1_f16,    cudaFuncAttributeMaxDynamicSharedMemorySize, smem1);
    cudaFuncSetAttribute(gemm2_ln_f16, cudaFuncAttributeMaxDynamicSharedMemorySize, smem2);

    size_t n4 = (size_t)NNODES * D / 4;
    zero_kernel<<<(unsigned)((n4 + 255) / 256), 256>>>();
    convw1t_kernel<<<dim3(32, 16), dim3(32, 8)>>>(W1);
    convw2t_kernel<<<dim3(16, 16), dim3(32, 8)>>>(W2);
    scatter_kernel<<<NEDGES * 128 / 256, 256>>>(edge_attr, edge_index);
    pack_kernel<<<MPAD, 256>>>(node);

    dim3 g1(4, MPAD / 128);
    gemm1_f16<<<g1, 256, smem1>>>(b1);

    gemm2_ln_f16<<<MPAD / 64, 512, smem2>>>(b2, gamma, beta, out);
}

// round 12
// speedup vs baseline: 5.6709x; 1.0224x over previous
#include <cuda_runtime.h>
#include <cuda_fp16.h>
#include <math.h>
#include <stdint.h>

#define NNODES 40962
#define NEDGES 327680
#define D 512
#define K1 1024
#define MPAD 41088  // 321*128

// Scratch (device globals; no allocations allowed)
__device__ float  g_edge_sum[(size_t)NNODES * D];   // 84 MB fp32 accum
__device__ __half g_x[(size_t)MPAD * K1];           // 84 MB  [node|edge_sum] fp16
__device__ __half g_h[(size_t)MPAD * D];            // 42 MB  hidden fp16
__device__ __half g_w1t[(size_t)D * K1];            // W1^T [n=512][k=1024] fp16
__device__ __half g_w2t[(size_t)D * D];             // W2^T [n=512][k=512]  fp16

__device__ __forceinline__ void mma_f16(float* c, const unsigned* a, const unsigned* b) {
    asm volatile(
        "mma.sync.aligned.m16n8k16.row.col.f32.f16.f16.f32 "
        "{%0,%1,%2,%3}, {%4,%5,%6,%7}, {%8,%9}, {%0,%1,%2,%3};\n"
        : "+f"(c[0]), "+f"(c[1]), "+f"(c[2]), "+f"(c[3])
        : "r"(a[0]), "r"(a[1]), "r"(a[2]), "r"(a[3]), "r"(b[0]), "r"(b[1]));
}
__device__ __forceinline__ void cp16(void* sdst, const void* gsrc) {
    unsigned sa = (unsigned)__cvta_generic_to_shared(sdst);
    asm volatile("cp.async.cg.shared.global [%0], [%1], 16;\n" :: "r"(sa), "l"(gsrc));
}
#define CP_COMMIT() asm volatile("cp.async.commit_group;\n")
#define CP_WAIT2()  asm volatile("cp.async.wait_group 2;\n")

__device__ __forceinline__ unsigned h2u(__half2 h) {
    return *reinterpret_cast<unsigned*>(&h);
}

// ---------------------------------------------------------------------------
__global__ void zero_kernel() {
    size_t i = (size_t)blockIdx.x * blockDim.x + threadIdx.x;
    size_t n4 = (size_t)NNODES * D / 4;
    if (i < n4) reinterpret_cast<float4*>(g_edge_sum)[i] = make_float4(0.f, 0.f, 0.f, 0.f);
}

// Column-split vectorized scatter: pass over columns [col0, col0+256).
// The RMW slice is then only 42 MB -> stays L2-resident under the
// .cs (evict-first) edge_attr stream. 64 threads per edge (64 float4s).
__global__ __launch_bounds__(256) void scatter_kernel(const float* __restrict__ edge_attr,
                                                      const int* __restrict__ edge_index,
                                                      int col0) {
    int idx = blockIdx.x * 256 + threadIdx.x;
    int e = idx >> 6;              // edge id
    int t = idx & 63;              // float4 slot within the 256-col half
    int r = __ldg(&edge_index[NEDGES + e]);
    const float4* src = reinterpret_cast<const float4*>(edge_attr + (size_t)e * D + col0 + t * 4);
    float4 v = __ldcs(src);
    float* dst = g_edge_sum + (size_t)r * D + col0 + t * 4;
    asm volatile("red.global.add.v4.f32 [%0], {%1,%2,%3,%4};\n"
                 :: "l"(dst), "f"(v.x), "f"(v.y), "f"(v.z), "f"(v.w)
                 : "memory");
}

// W1 [k=1024][n=512] -> g_w1t [n][k] fp16
__global__ void convw1t_kernel(const float* __restrict__ W1) {
    __shared__ float t[32][33];
    int bx = blockIdx.x;   // k tile (32 tiles)
    int by = blockIdx.y;   // n tile (16 tiles)
    int x = threadIdx.x, y = threadIdx.y;  // 32 x 8
#pragma unroll
    for (int i = 0; i < 32; i += 8)
        t[y + i][x] = W1[(size_t)(bx * 32 + y + i) * D + by * 32 + x];
    __syncthreads();
#pragma unroll
    for (int i = 0; i < 32; i += 8)
        g_w1t[(size_t)(by * 32 + y + i) * K1 + bx * 32 + x] = __float2half_rn(t[x][y + i]);
}

// W2 [k=512][n=512] -> g_w2t [n][k] fp16
__global__ void convw2t_kernel(const float* __restrict__ W2) {
    __shared__ float t[32][33];
    int bx = blockIdx.x;   // k tile (16)
    int by = blockIdx.y;   // n tile (16)
    int x = threadIdx.x, y = threadIdx.y;
#pragma unroll
    for (int i = 0; i < 32; i += 8)
        t[y + i][x] = W2[(size_t)(bx * 32 + y + i) * D + by * 32 + x];
    __syncthreads();
#pragma unroll
    for (int i = 0; i < 32; i += 8)
        g_w2t[(size_t)(by * 32 + y + i) * D + bx * 32 + x] = __float2half_rn(t[x][y + i]);
}

// g_x[r] = fp16([node[r] | edge_sum[r]]), zero for pad rows
__global__ void pack_kernel(const float* __restrict__ node) {
    int r = blockIdx.x;
    int c = threadIdx.x * 4;
    float4 v = make_float4(0.f, 0.f, 0.f, 0.f);
    if (r < NNODES) {
        v = (c < D)
            ? *reinterpret_cast<const float4*>(node + (size_t)r * D + c)
            : *reinterpret_cast<const float4*>(g_edge_sum + (size_t)r * D + (c - D));
    }
    __half2 h01 = __floats2half2_rn(v.x, v.y);
    __half2 h23 = __floats2half2_rn(v.z, v.w);
    uint2 o = make_uint2(h2u(h01), h2u(h23));
    *reinterpret_cast<uint2*>(g_x + (size_t)r * K1 + c) = o;
}

// ---------------------------------------------------------------------------
// GEMM1: h = silu(g_x @ W1 + b1)   M=MPAD K=1024 N=512, fp16 mma m16n8k16.
// BM=128 BN=128 BK=32. 256 thr, 8 warps (2m x 4n), warp tile 64x32.
// A,B smem tiles: [128 rows][16 half2 words], word stride 20 (conflict-free).
// 4-stage cp.async.
// ---------------------------------------------------------------------------
#define G1_RS 20                  // row stride in 32-bit words
#define G1_TILE (128 * G1_RS)     // words per operand tile
#define G1_STW (2 * G1_TILE)      // words per stage (A+B)
__global__ __launch_bounds__(256, 2) void gemm1_f16(const float* __restrict__ b1) {
    extern __shared__ unsigned smw[];
    int tid = threadIdx.x, lane = tid & 31, wid = tid >> 5;
    int warp_m = wid >> 2, warp_n = wid & 3;
    int g = lane >> 2, tig = lane & 3;
    int bx = blockIdx.x, by = blockIdx.y;

    const __half* aSrc = g_x + (size_t)(by * 128) * K1;
    const __half* bSrc = g_w1t + (size_t)(bx * 128) * K1;

    float acc[4][4][4] = {};

#define G1_ISSUE(kt, st)                                                         \
    {                                                                            \
        unsigned* base = smw + (st) * G1_STW;                                    \
        _Pragma("unroll")                                                        \
        for (int t = 0; t < 2; ++t) {                                            \
            int idx = tid + t * 256;                                             \
            int row = idx >> 2, wq = (idx & 3) * 4;                              \
            cp16(base + row * G1_RS + wq,                                        \
                 aSrc + (size_t)row * K1 + (kt) * 32 + wq * 2);                  \
        }                                                                        \
        _Pragma("unroll")                                                        \
        for (int t = 0; t < 2; ++t) {                                            \
            int idx = tid + t * 256;                                             \
            int row = idx >> 2, wq = (idx & 3) * 4;                              \
            cp16(base + G1_TILE + row * G1_RS + wq,                              \
                 bSrc + (size_t)row * K1 + (kt) * 32 + wq * 2);                  \
        }                                                                        \
        CP_COMMIT();                                                             \
    }

    G1_ISSUE(0, 0);
    G1_ISSUE(1, 1);
    G1_ISSUE(2, 2);

    for (int kt = 0; kt < 32; ++kt) {
        CP_WAIT2();
        __syncthreads();
        const unsigned* cA = smw + (kt & 3) * G1_STW;
        const unsigned* cB = cA + G1_TILE;
#pragma unroll
        for (int ks = 0; ks < 2; ++ks) {
            unsigned a[4][4], b[4][2];
#pragma unroll
            for (int i = 0; i < 4; ++i) {
                int base = (warp_m * 64 + i * 16 + g) * G1_RS + ks * 8 + tig;
                a[i][0] = cA[base];
                a[i][1] = cA[base + 8 * G1_RS];
                a[i][2] = cA[base + 4];
                a[i][3] = cA[base + 8 * G1_RS + 4];
            }
#pragma unroll
            for (int j = 0; j < 4; ++j) {
                int nb = (warp_n * 32 + j * 8 + g) * G1_RS + ks * 8 + tig;
                b[j][0] = cB[nb];
                b[j][1] = cB[nb + 4];
            }
#pragma unroll
            for (int i = 0; i < 4; ++i)
#pragma unroll
                for (int j = 0; j < 4; ++j)
                    mma_f16(acc[i][j], a[i], b[j]);
        }
        if (kt + 3 < 32) {
            G1_ISSUE(kt + 3, (kt + 3) & 3);
        } else {
            CP_COMMIT();
        }
    }

    // epilogue: bias + silu -> fp16 g_h
#pragma unroll
    for (int i = 0; i < 4; ++i) {
        int r0 = by * 128 + warp_m * 64 + i * 16 + g;
#pragma unroll
        for (int j = 0; j < 4; ++j) {
            int c0 = bx * 128 + warp_n * 32 + j * 8 + tig * 2;
            float bb0 = __ldg(&b1[c0]), bb1 = __ldg(&b1[c0 + 1]);
            float v0 = acc[i][j][0] + bb0;
            float v1 = acc[i][j][1] + bb1;
            float v2 = acc[i][j][2] + bb0;
            float v3 = acc[i][j][3] + bb1;
            v0 = v0 / (1.f + __expf(-v0));
            v1 = v1 / (1.f + __expf(-v1));
            v2 = v2 / (1.f + __expf(-v2));
            v3 = v3 / (1.f + __expf(-v3));
            *reinterpret_cast<unsigned*>(&g_h[(size_t)r0 * D + c0]) =
                h2u(__floats2half2_rn(v0, v1));
            *reinterpret_cast<unsigned*>(&g_h[(size_t)(r0 + 8) * D + c0]) =
                h2u(__floats2half2_rn(v2, v3));
        }
    }
}

// ---------------------------------------------------------------------------
// GEMM2 + bias + LayerNorm fused.  BM=64 BN=512 (full rows) BK=32, fp16 mma.
// 512 thr, 16 warps (2m x 8n), warp tile 32x64. 4-stage cp.async.
// ---------------------------------------------------------------------------
#define G2_RS 20
#define G2_ATILE (64 * G2_RS)     // 1280 words
#define G2_BTILE (512 * G2_RS)    // 10240 words
#define G2_STW (G2_ATILE + G2_BTILE)
__global__ __launch_bounds__(512, 1) void gemm2_ln_f16(const float* __restrict__ b2,
                                                       const float* __restrict__ gamma,
                                                       const float* __restrict__ beta,
                                                       float* __restrict__ out) {
    extern __shared__ unsigned smw[];
    __shared__ float mean_s[64], rstd_s[64];

    int tid = threadIdx.x, lane = tid & 31, wid = tid >> 5;
    int warp_m = wid >> 3, warp_n = wid & 7;
    int g = lane >> 2, tig = lane & 3;
    int bm = blockIdx.x;

    const __half* aSrc = g_h + (size_t)(bm * 64) * D;

    float acc[2][8][4] = {};

#define G2_ISSUE(kt, st)                                                         \
    {                                                                            \
        unsigned* base = smw + (st) * G2_STW;                                    \
        if (tid < 256) {                                                         \
            int row = tid >> 2, wq = (tid & 3) * 4;                              \
            cp16(base + row * G2_RS + wq,                                        \
                 aSrc + (size_t)row * D + (kt) * 32 + wq * 2);                   \
        }                                                                        \
        _Pragma("unroll")                                                        \
        for (int t = 0; t < 4; ++t) {                                            \
            int idx = tid + t * 512;                                             \
            int row = idx >> 2, wq = (idx & 3) * 4;                              \
            cp16(base + G2_ATILE + row * G2_RS + wq,                             \
                 g_w2t + (size_t)row * D + (kt) * 32 + wq * 2);                  \
        }                                                                        \
        CP_COMMIT();                                                             \
    }

    G2_ISSUE(0, 0);
    G2_ISSUE(1, 1);
    G2_ISSUE(2, 2);

    for (int kt = 0; kt < 16; ++kt) {
        CP_WAIT2();
        __syncthreads();
        const unsigned* cA = smw + (kt & 3) * G2_STW;
        const unsigned* cB = cA + G2_ATILE;
#pragma unroll
        for (int ks = 0; ks < 2; ++ks) {
            unsigned a[2][4], b[8][2];
#pragma unroll
            for (int i = 0; i < 2; ++i) {
                int base = (warp_m * 32 + i * 16 + g) * G2_RS + ks * 8 + tig;
                a[i][0] = cA[base];
                a[i][1] = cA[base + 8 * G2_RS];
                a[i][2] = cA[base + 4];
                a[i][3] = cA[base + 8 * G2_RS + 4];
            }
#pragma unroll
            for (int j = 0; j < 8; ++j) {
                int nb = (warp_n * 64 + j * 8 + g) * G2_RS + ks * 8 + tig;
                b[j][0] = cB[nb];
                b[j][1] = cB[nb + 4];
            }
#pragma unroll
            for (int i = 0; i < 2; ++i)
#pragma unroll
                for (int j = 0; j < 8; ++j)
                    mma_f16(acc[i][j], a[i], b[j]);
        }
        if (kt + 3 < 16) {
            G2_ISSUE(kt + 3, (kt + 3) & 3);
        } else {
            CP_COMMIT();
        }
    }

    // bias + per-row partial sums
    float rsum[4] = {0.f, 0.f, 0.f, 0.f};
    float rsq[4]  = {0.f, 0.f, 0.f, 0.f};
#pragma unroll
    for (int i = 0; i < 2; ++i)
#pragma unroll
        for (int j = 0; j < 8; ++j) {
            int c0 = warp_n * 64 + j * 8 + tig * 2;
            float bb0 = __ldg(&b2[c0]), bb1 = __ldg(&b2[c0 + 1]);
            float v0 = acc[i][j][0] + bb0;
            float v1 = acc[i][j][1] + bb1;
            float v2 = acc[i][j][2] + bb0;
            float v3 = acc[i][j][3] + bb1;
            acc[i][j][0] = v0; acc[i][j][1] = v1;
            acc[i][j][2] = v2; acc[i][j][3] = v3;
            rsum[i * 2 + 0] += v0 + v1;
            rsq [i * 2 + 0] += v0 * v0 + v1 * v1;
            rsum[i * 2 + 1] += v2 + v3;
            rsq [i * 2 + 1] += v2 * v2 + v3 * v3;
        }
#pragma unroll
    for (int h = 0; h < 4; ++h) {
        rsum[h] += __shfl_xor_sync(0xffffffffu, rsum[h], 1);
        rsum[h] += __shfl_xor_sync(0xffffffffu, rsum[h], 2);
        rsq[h]  += __shfl_xor_sync(0xffffffffu, rsq[h], 1);
        rsq[h]  += __shfl_xor_sync(0xffffffffu, rsq[h], 2);
    }
    __syncthreads();  // mainloop smem reads done before reuse
    float* red = reinterpret_cast<float*>(smw);  // 1024 floats
    if (tig == 0) {
#pragma unroll
        for (int h = 0; h < 4; ++h) {
            int row = warp_m * 32 + (h >> 1) * 16 + (h & 1) * 8 + g;
            red[row * 8 + warp_n] = rsum[h];
            red[512 + row * 8 + warp_n] = rsq[h];
        }
    }
    __syncthreads();
    if (tid < 64) {
        float s = 0.f, q = 0.f;
#pragma unroll
        for (int w = 0; w < 8; ++w) {
            s += red[tid * 8 + w];
            q += red[512 + tid * 8 + w];
        }
        float mean = s * (1.0f / 512.0f);
        float var = q * (1.0f / 512.0f) - mean * mean;
        mean_s[tid] = mean;
        rstd_s[tid] = rsqrtf(var + 1e-5f);
    }
    __syncthreads();

#pragma unroll
    for (int i = 0; i < 2; ++i)
#pragma unroll
        for (int hi = 0; hi < 2; ++hi) {
            int row = warp_m * 32 + i * 16 + hi * 8 + g;
            int grow = bm * 64 + row;
            if (grow < NNODES) {
                float mean = mean_s[row], rstd = rstd_s[row];
#pragma unroll
                for (int j = 0; j < 8; ++j) {
                    int c0 = warp_n * 64 + j * 8 + tig * 2;
                    float ga0 = __ldg(&gamma[c0]), ga1 = __ldg(&gamma[c0 + 1]);
                    float be0 = __ldg(&beta[c0]),  be1 = __ldg(&beta[c0 + 1]);
                    float y0 = (acc[i][j][hi * 2 + 0] - mean) * rstd * ga0 + be0;
                    float y1 = (acc[i][j][hi * 2 + 1] - mean) * rstd * ga1 + be1;
                    *reinterpret_cast<float2*>(&out[(size_t)grow * D + c0]) =
                        make_float2(y0, y1);
                }
            }
        }
}

// ---------------------------------------------------------------------------
extern "C" void kernel_launch(void* const* d_in, const int* in_sizes, int n_in,
                              void* d_out, int out_size) {
    const float* node       = (const float*)d_in[0];
    const int*   edge_index = (const int*)  d_in[1];
    const float* edge_attr  = (const float*)d_in[2];
    const float* W1         = (const float*)d_in[3];
    const float* b1         = (const float*)d_in[4];
    const float* W2         = (const float*)d_in[5];
    const float* b2         = (const float*)d_in[6];
    const float* gamma      = (const float*)d_in[7];
    const float* beta       = (const float*)d_in[8];
    float* out = (float*)d_out;

    int smem1 = 4 * G1_STW * sizeof(unsigned);  // 81920 B
    int smem2 = 4 * G2_STW * sizeof(unsigned);  // 184320 B
    cudaFuncSetAttribute(gemm1_f16,    cudaFuncAttributeMaxDynamicSharedMemorySize, smem1);
    cudaFuncSetAttribute(gemm2_ln_f16, cudaFuncAttributeMaxDynamicSharedMemorySize, smem2);

    size_t n4 = (size_t)NNODES * D / 4;
    zero_kernel<<<(unsigned)((n4 + 255) / 256), 256>>>();
    convw1t_kernel<<<dim3(32, 16), dim3(32, 8)>>>(W1);
    convw2t_kernel<<<dim3(16, 16), dim3(32, 8)>>>(W2);
    // column-split scatter: two passes, each with a 42MB L2-resident RMW slice
    scatter_kernel<<<NEDGES * 64 / 256, 256>>>(edge_attr, edge_index, 0);
    scatter_kernel<<<NEDGES * 64 / 256, 256>>>(edge_attr, edge_index, 256);
    pack_kernel<<<MPAD, 256>>>(node);

    dim3 g1(4, MPAD / 128);
    gemm1_f16<<<g1, 256, smem1>>>(b1);

    gemm2_ln_f16<<<MPAD / 64, 512, smem2>>>(b2, gamma, beta, out);
}

// round 13
// speedup vs baseline: 6.1132x; 1.0780x over previous
#include <cuda_runtime.h>
#include <cuda_fp16.h>
#include <math.h>
#include <stdint.h>

#define NNODES 40962
#define NEDGES 327680
#define D 512
#define K1 1024
#define MPAD 41088  // 321*128

// Scratch (device globals; no allocations allowed)
__device__ float  g_edge_sum[(size_t)NNODES * D];   // 84 MB fp32 accum
__device__ __half g_x[(size_t)MPAD * K1];           // 84 MB  [node|edge_sum] fp16
__device__ __half g_h[(size_t)MPAD * D];            // 42 MB  hidden fp16
__device__ __half g_w1t[(size_t)D * K1];            // W1^T [n=512][k=1024] fp16
__device__ __half g_w2t[(size_t)D * D];             // W2^T [n=512][k=512]  fp16

__device__ __forceinline__ void mma_f16(float* c, const unsigned* a, const unsigned* b) {
    asm volatile(
        "mma.sync.aligned.m16n8k16.row.col.f32.f16.f16.f32 "
        "{%0,%1,%2,%3}, {%4,%5,%6,%7}, {%8,%9}, {%0,%1,%2,%3};\n"
        : "+f"(c[0]), "+f"(c[1]), "+f"(c[2]), "+f"(c[3])
        : "r"(a[0]), "r"(a[1]), "r"(a[2]), "r"(a[3]), "r"(b[0]), "r"(b[1]));
}
__device__ __forceinline__ void ldsm4(unsigned& r0, unsigned& r1, unsigned& r2,
                                      unsigned& r3, unsigned saddr) {
    asm volatile("ldmatrix.sync.aligned.m8n8.x4.shared.b16 {%0,%1,%2,%3}, [%4];"
                 : "=r"(r0), "=r"(r1), "=r"(r2), "=r"(r3) : "r"(saddr));
}
__device__ __forceinline__ void cp16(void* sdst, const void* gsrc) {
    unsigned sa = (unsigned)__cvta_generic_to_shared(sdst);
    asm volatile("cp.async.cg.shared.global [%0], [%1], 16;\n" :: "r"(sa), "l"(gsrc));
}
#define CP_COMMIT() asm volatile("cp.async.commit_group;\n")
#define CP_WAIT2()  asm volatile("cp.async.wait_group 2;\n")

__device__ __forceinline__ unsigned h2u(__half2 h) {
    return *reinterpret_cast<unsigned*>(&h);
}

// ---------------------------------------------------------------------------
__global__ void zero_kernel() {
    size_t i = (size_t)blockIdx.x * blockDim.x + threadIdx.x;
    size_t n4 = (size_t)NNODES * D / 4;
    if (i < n4) reinterpret_cast<float4*>(g_edge_sum)[i] = make_float4(0.f, 0.f, 0.f, 0.f);
}

// Column-split scatter, 2 edges per thread for MLP=2.
// Pass handles columns [col0, col0+256); RMW slice 42MB stays L2-resident
// under the .cs streaming loads.
__global__ __launch_bounds__(256) void scatter_kernel(const float* __restrict__ edge_attr,
                                                      const int* __restrict__ edge_index,
                                                      int col0) {
    int idx = blockIdx.x * 256 + threadIdx.x;
    int p = idx >> 6;              // edge pair
    int t = idx & 63;              // float4 slot within the 256-col half
    int e0 = p * 2;
    int2 rr = *reinterpret_cast<const int2*>(edge_index + NEDGES + e0);
    const float* s0 = edge_attr + (size_t)e0 * D + col0 + t * 4;
    float4 v0 = __ldcs(reinterpret_cast<const float4*>(s0));
    float4 v1 = __ldcs(reinterpret_cast<const float4*>(s0 + D));
    float* d0 = g_edge_sum + (size_t)rr.x * D + col0 + t * 4;
    float* d1 = g_edge_sum + (size_t)rr.y * D + col0 + t * 4;
    asm volatile("red.global.add.v4.f32 [%0], {%1,%2,%3,%4};\n"
                 :: "l"(d0), "f"(v0.x), "f"(v0.y), "f"(v0.z), "f"(v0.w) : "memory");
    asm volatile("red.global.add.v4.f32 [%0], {%1,%2,%3,%4};\n"
                 :: "l"(d1), "f"(v1.x), "f"(v1.y), "f"(v1.z), "f"(v1.w) : "memory");
}

// W1 [k=1024][n=512] -> g_w1t [n][k] fp16
__global__ void convw1t_kernel(const float* __restrict__ W1) {
    __shared__ float t[32][33];
    int bx = blockIdx.x;   // k tile (32 tiles)
    int by = blockIdx.y;   // n tile (16 tiles)
    int x = threadIdx.x, y = threadIdx.y;  // 32 x 8
#pragma unroll
    for (int i = 0; i < 32; i += 8)
        t[y + i][x] = W1[(size_t)(bx * 32 + y + i) * D + by * 32 + x];
    __syncthreads();
#pragma unroll
    for (int i = 0; i < 32; i += 8)
        g_w1t[(size_t)(by * 32 + y + i) * K1 + bx * 32 + x] = __float2half_rn(t[x][y + i]);
}

// W2 [k=512][n=512] -> g_w2t [n][k] fp16
__global__ void convw2t_kernel(const float* __restrict__ W2) {
    __shared__ float t[32][33];
    int bx = blockIdx.x;   // k tile (16)
    int by = blockIdx.y;   // n tile (16)
    int x = threadIdx.x, y = threadIdx.y;
#pragma unroll
    for (int i = 0; i < 32; i += 8)
        t[y + i][x] = W2[(size_t)(bx * 32 + y + i) * D + by * 32 + x];
    __syncthreads();
#pragma unroll
    for (int i = 0; i < 32; i += 8)
        g_w2t[(size_t)(by * 32 + y + i) * D + bx * 32 + x] = __float2half_rn(t[x][y + i]);
}

// g_x[r] = fp16([node[r] | edge_sum[r]]), zero for pad rows
__global__ void pack_kernel(const float* __restrict__ node) {
    int r = blockIdx.x;
    int c = threadIdx.x * 4;
    float4 v = make_float4(0.f, 0.f, 0.f, 0.f);
    if (r < NNODES) {
        v = (c < D)
            ? *reinterpret_cast<const float4*>(node + (size_t)r * D + c)
            : *reinterpret_cast<const float4*>(g_edge_sum + (size_t)r * D + (c - D));
    }
    __half2 h01 = __floats2half2_rn(v.x, v.y);
    __half2 h23 = __floats2half2_rn(v.z, v.w);
    uint2 o = make_uint2(h2u(h01), h2u(h23));
    *reinterpret_cast<uint2*>(g_x + (size_t)r * K1 + c) = o;
}

// ---------------------------------------------------------------------------
// GEMM1: h = silu(g_x @ W1 + b1)   M=MPAD K=1024 N=512, fp16 mma m16n8k16.
// BM=128 BN=128 BK=32. 256 thr, 8 warps (2m x 4n), warp tile 64x32.
// A,B smem tiles: [128 rows][16 half2 words], word stride 20.
// Fragment loads via ldmatrix.x4 (rows stride 80B -> conflict-free).
// 4-stage cp.async.
// ---------------------------------------------------------------------------
#define G1_RS 20                  // row stride in 32-bit words
#define G1_TILE (128 * G1_RS)     // words per operand tile
#define G1_STW (2 * G1_TILE)      // words per stage (A+B)
__global__ __launch_bounds__(256, 2) void gemm1_f16(const float* __restrict__ b1) {
    extern __shared__ unsigned smw[];
    int tid = threadIdx.x, lane = tid & 31, wid = tid >> 5;
    int warp_m = wid >> 2, warp_n = wid & 3;
    int g = lane >> 2, tig = lane & 3;
    int bx = blockIdx.x, by = blockIdx.y;

    unsigned sbase = (unsigned)__cvta_generic_to_shared(smw);

    // ldmatrix lane-address components
    int t4 = lane >> 3, rr = lane & 7;
    int a_row = (t4 & 1) * 8 + rr;     // row offset within mtile
    int a_wof = (t4 >> 1) * 4;         // word offset within ks group
    int b_row = (t4 >> 1) * 8 + rr;    // row offset within ntile-pair
    int b_wof = (t4 & 1) * 4;

    const __half* aSrc = g_x + (size_t)(by * 128) * K1;
    const __half* bSrc = g_w1t + (size_t)(bx * 128) * K1;

    float acc[4][4][4] = {};

#define G1_ISSUE(kt, st)                                                         \
    {                                                                            \
        unsigned* base = smw + (st) * G1_STW;                                    \
        _Pragma("unroll")                                                        \
        for (int t = 0; t < 2; ++t) {                                            \
            int idx = tid + t * 256;                                             \
            int row = idx >> 2, wq = (idx & 3) * 4;                              \
            cp16(base + row * G1_RS + wq,                                        \
                 aSrc + (size_t)row * K1 + (kt) * 32 + wq * 2);                  \
        }                                                                        \
        _Pragma("unroll")                                                        \
        for (int t = 0; t < 2; ++t) {                                            \
            int idx = tid + t * 256;                                             \
            int row = idx >> 2, wq = (idx & 3) * 4;                              \
            cp16(base + G1_TILE + row * G1_RS + wq,                              \
                 bSrc + (size_t)row * K1 + (kt) * 32 + wq * 2);                  \
        }                                                                        \
        CP_COMMIT();                                                             \
    }

    G1_ISSUE(0, 0);
    G1_ISSUE(1, 1);
    G1_ISSUE(2, 2);

    for (int kt = 0; kt < 32; ++kt) {
        CP_WAIT2();
        __syncthreads();
        unsigned cbase = sbase + ((kt & 3) * G1_STW) * 4;
#pragma unroll
        for (int ks = 0; ks < 2; ++ks) {
            unsigned a[4][4], b[4][2];
#pragma unroll
            for (int i = 0; i < 4; ++i) {
                unsigned addr = cbase +
                    ((warp_m * 64 + i * 16 + a_row) * G1_RS + ks * 8 + a_wof) * 4;
                ldsm4(a[i][0], a[i][1], a[i][2], a[i][3], addr);
            }
#pragma unroll
            for (int j2 = 0; j2 < 2; ++j2) {
                unsigned addr = cbase +
                    (G1_TILE + (warp_n * 32 + j2 * 16 + b_row) * G1_RS + ks * 8 + b_wof) * 4;
                ldsm4(b[2 * j2][0], b[2 * j2][1], b[2 * j2 + 1][0], b[2 * j2 + 1][1], addr);
            }
#pragma unroll
            for (int i = 0; i < 4; ++i)
#pragma unroll
                for (int j = 0; j < 4; ++j)
                    mma_f16(acc[i][j], a[i], b[j]);
        }
        if (kt + 3 < 32) {
            G1_ISSUE(kt + 3, (kt + 3) & 3);
        } else {
            CP_COMMIT();
        }
    }

    // epilogue: bias + silu -> fp16 g_h
#pragma unroll
    for (int i = 0; i < 4; ++i) {
        int r0 = by * 128 + warp_m * 64 + i * 16 + g;
#pragma unroll
        for (int j = 0; j < 4; ++j) {
            int c0 = bx * 128 + warp_n * 32 + j * 8 + tig * 2;
            float bb0 = __ldg(&b1[c0]), bb1 = __ldg(&b1[c0 + 1]);
            float v0 = acc[i][j][0] + bb0;
            float v1 = acc[i][j][1] + bb1;
            float v2 = acc[i][j][2] + bb0;
            float v3 = acc[i][j][3] + bb1;
            v0 = v0 / (1.f + __expf(-v0));
            v1 = v1 / (1.f + __expf(-v1));
            v2 = v2 / (1.f + __expf(-v2));
            v3 = v3 / (1.f + __expf(-v3));
            *reinterpret_cast<unsigned*>(&g_h[(size_t)r0 * D + c0]) =
                h2u(__floats2half2_rn(v0, v1));
            *reinterpret_cast<unsigned*>(&g_h[(size_t)(r0 + 8) * D + c0]) =
                h2u(__floats2half2_rn(v2, v3));
        }
    }
}

// ---------------------------------------------------------------------------
// GEMM2 + bias + LayerNorm fused.  BM=64 BN=512 (full rows) BK=32, fp16 mma.
// 512 thr, 16 warps (2m x 8n), warp tile 32x64. ldmatrix frag loads.
// 4-stage cp.async.
// ---------------------------------------------------------------------------
#define G2_RS 20
#define G2_ATILE (64 * G2_RS)     // 1280 words
#define G2_BTILE (512 * G2_RS)    // 10240 words
#define G2_STW (G2_ATILE + G2_BTILE)
__global__ __launch_bounds__(512, 1) void gemm2_ln_f16(const float* __restrict__ b2,
                                                       const float* __restrict__ gamma,
                                                       const float* __restrict__ beta,
                                                       float* __restrict__ out) {
    extern __shared__ unsigned smw[];
    __shared__ float mean_s[64], rstd_s[64];

    int tid = threadIdx.x, lane = tid & 31, wid = tid >> 5;
    int warp_m = wid >> 3, warp_n = wid & 7;
    int g = lane >> 2, tig = lane & 3;
    int bm = blockIdx.x;

    unsigned sbase = (unsigned)__cvta_generic_to_shared(smw);
    int t4 = lane >> 3, rr = lane & 7;
    int a_row = (t4 & 1) * 8 + rr;
    int a_wof = (t4 >> 1) * 4;
    int b_row = (t4 >> 1) * 8 + rr;
    int b_wof = (t4 & 1) * 4;

    const __half* aSrc = g_h + (size_t)(bm * 64) * D;

    float acc[2][8][4] = {};

#define G2_ISSUE(kt, st)                                                         \
    {                                                                            \
        unsigned* base = smw + (st) * G2_STW;                                    \
        if (tid < 256) {                                                         \
            int row = tid >> 2, wq = (tid & 3) * 4;                              \
            cp16(base + row * G2_RS + wq,                                        \
                 aSrc + (size_t)row * D + (kt) * 32 + wq * 2);                   \
        }                                                                        \
        _Pragma("unroll")                                                        \
        for (int t = 0; t < 4; ++t) {                                            \
            int idx = tid + t * 512;                                             \
            int row = idx >> 2, wq = (idx & 3) * 4;                              \
            cp16(base + G2_ATILE + row * G2_RS + wq,                             \
                 g_w2t + (size_t)row * D + (kt) * 32 + wq * 2);                  \
        }                                                                        \
        CP_COMMIT();                                                             \
    }

    G2_ISSUE(0, 0);
    G2_ISSUE(1, 1);
    G2_ISSUE(2, 2);

    for (int kt = 0; kt < 16; ++kt) {
        CP_WAIT2();
        __syncthreads();
        unsigned cbase = sbase + ((kt & 3) * G2_STW) * 4;
#pragma unroll
        for (int ks = 0; ks < 2; ++ks) {
            unsigned a[2][4], b[8][2];
#pragma unroll
            for (int i = 0; i < 2; ++i) {
                unsigned addr = cbase +
                    ((warp_m * 32 + i * 16 + a_row) * G2_RS + ks * 8 + a_wof) * 4;
                ldsm4(a[i][0], a[i][1], a[i][2], a[i][3], addr);
            }
#pragma unroll
            for (int j2 = 0; j2 < 4; ++j2) {
                unsigned addr = cbase +
                    (G2_ATILE + (warp_n * 64 + j2 * 16 + b_row) * G2_RS + ks * 8 + b_wof) * 4;
                ldsm4(b[2 * j2][0], b[2 * j2][1], b[2 * j2 + 1][0], b[2 * j2 + 1][1], addr);
            }
#pragma unroll
            for (int i = 0; i < 2; ++i)
#pragma unroll
                for (int j = 0; j < 8; ++j)
                    mma_f16(acc[i][j], a[i], b[j]);
        }
        if (kt + 3 < 16) {
            G2_ISSUE(kt + 3, (kt + 3) & 3);
        } else {
            CP_COMMIT();
        }
    }

    // bias + per-row partial sums
    float rsum[4] = {0.f, 0.f, 0.f, 0.f};
    float rsq[4]  = {0.f, 0.f, 0.f, 0.f};
#pragma unroll
    for (int i = 0; i < 2; ++i)
#pragma unroll
        for (int j = 0; j < 8; ++j) {
            int c0 = warp_n * 64 + j * 8 + tig * 2;
            float bb0 = __ldg(&b2[c0]), bb1 = __ldg(&b2[c0 + 1]);
            float v0 = acc[i][j][0] + bb0;
            float v1 = acc[i][j][1] + bb1;
            float v2 = acc[i][j][2] + bb0;
            float v3 = acc[i][j][3] + bb1;
            acc[i][j][0] = v0; acc[i][j][1] = v1;
            acc[i][j][2] = v2; acc[i][j][3] = v3;
            rsum[i * 2 + 0] += v0 + v1;
            rsq [i * 2 + 0] += v0 * v0 + v1 * v1;
            rsum[i * 2 + 1] += v2 + v3;
            rsq [i * 2 + 1] += v2 * v2 + v3 * v3;
        }
#pragma unroll
    for (int h = 0; h < 4; ++h) {
        rsum[h] += __shfl_xor_sync(0xffffffffu, rsum[h], 1);
        rsum[h] += __shfl_xor_sync(0xffffffffu, rsum[h], 2);
        rsq[h]  += __shfl_xor_sync(0xffffffffu, rsq[h], 1);
        rsq[h]  += __shfl_xor_sync(0xffffffffu, rsq[h], 2);
    }
    __syncthreads();  // mainloop smem reads done before reuse
    float* red = reinterpret_cast<float*>(smw);  // 1024 floats
    if (tig == 0) {
#pragma unroll
        for (int h = 0; h < 4; ++h) {
            int row = warp_m * 32 + (h >> 1) * 16 + (h & 1) * 8 + g;
            red[row * 8 + warp_n] = rsum[h];
            red[512 + row * 8 + warp_n] = rsq[h];
        }
    }
    __syncthreads();
    if (tid < 64) {
        float s = 0.f, q = 0.f;
#pragma unroll
        for (int w = 0; w < 8; ++w) {
            s += red[tid * 8 + w];
            q += red[512 + tid * 8 + w];
        }
        float mean = s * (1.0f / 512.0f);
        float var = q * (1.0f / 512.0f) - mean * mean;
        mean_s[tid] = mean;
        rstd_s[tid] = rsqrtf(var + 1e-5f);
    }
    __syncthreads();

#pragma unroll
    for (int i = 0; i < 2; ++i)
#pragma unroll
        for (int hi = 0; hi < 2; ++hi) {
            int row = warp_m * 32 + i * 16 + hi * 8 + g;
            int grow = bm * 64 + row;
            if (grow < NNODES) {
                float mean = mean_s[row], rstd = rstd_s[row];
#pragma unroll
                for (int j = 0; j < 8; ++j) {
                    int c0 = warp_n * 64 + j * 8 + tig * 2;
                    float ga0 = __ldg(&gamma[c0]), ga1 = __ldg(&gamma[c0 + 1]);
                    float be0 = __ldg(&beta[c0]),  be1 = __ldg(&beta[c0 + 1]);
                    float y0 = (acc[i][j][hi * 2 + 0] - mean) * rstd * ga0 + be0;
                    float y1 = (acc[i][j][hi * 2 + 1] - mean) * rstd * ga1 + be1;
                    *reinterpret_cast<float2*>(&out[(size_t)grow * D + c0]) =
                        make_float2(y0, y1);
                }
            }
        }
}

// ---------------------------------------------------------------------------
extern "C" void kernel_launch(void* const* d_in, const int* in_sizes, int n_in,
                              void* d_out, int out_size) {
    const float* node       = (const float*)d_in[0];
    const int*   edge_index = (const int*)  d_in[1];
    const float* edge_attr  = (const float*)d_in[2];
    const float* W1         = (const float*)d_in[3];
    const float* b1         = (const float*)d_in[4];
    const float* W2         = (const float*)d_in[5];
    const float* b2         = (const float*)d_in[6];
    const float* gamma      = (const float*)d_in[7];
    const float* beta       = (const float*)d_in[8];
    float* out = (float*)d_out;

    int smem1 = 4 * G1_STW * sizeof(unsigned);  // 81920 B
    int smem2 = 4 * G2_STW * sizeof(unsigned);  // 184320 B
    cudaFuncSetAttribute(gemm1_f16,    cudaFuncAttributeMaxDynamicSharedMemorySize, smem1);
    cudaFuncSetAttribute(gemm2_ln_f16, cudaFuncAttributeMaxDynamicSharedMemorySize, smem2);

    size_t n4 = (size_t)NNODES * D / 4;
    zero_kernel<<<(unsigned)((n4 + 255) / 256), 256>>>();
    convw1t_kernel<<<dim3(32, 16), dim3(32, 8)>>>(W1);
    convw2t_kernel<<<dim3(16, 16), dim3(32, 8)>>>(W2);
    // column-split scatter: two passes, 2 edges/thread (MLP=2)
    scatter_kernel<<<NEDGES * 64 / 512, 256>>>(edge_attr, edge_index, 0);
    scatter_kernel<<<NEDGES * 64 / 512, 256>>>(edge_attr, edge_index, 256);
    pack_kernel<<<MPAD, 256>>>(node);

    dim3 g1(4, MPAD / 128);
    gemm1_f16<<<g1, 256, smem1>>>(b1);

    gemm2_ln_f16<<<MPAD / 64, 512, smem2>>>(b2, gamma, beta, out);
}